// round 7
// baseline (speedup 1.0000x reference)
#include <cuda_runtime.h>
#include <cuda_bf16.h>
#include <math.h>
#include <stdint.h>

#define NUM_H 24
#define LQ 1280
#define LK 2304

// ---------------- scratch (device globals; no allocations) ----------------
__device__ float g_q[4*24*1280*64];      // (B,H,LQ,64)
__device__ float g_k[4*24*2304*64];      // (B,H,LK,64)
__device__ float g_v[4*24*2304*64];
__device__ float g_ah[4*1024*1536];      // attention out, hidden part (B,S,D)
__device__ float g_ae[4*256*1536];       // attention out, encoder part (B,SE,D)
__device__ float g_mq[6144], g_sq[6144], g_mk[6144], g_sk[6144];
// fragment-packed K/V: per (bh, kv-tile) 1024 uint4 slots, slot=(s*8+nt)*32+lane,
// uint4 = (b0h, b1h, b0l, b1l) exactly as consumed by mma lanes.
__device__ uint4 g_kf[96*36*1024];
__device__ uint4 g_vf[96*36*1024];

// ---------------- bf16 helpers ----------------
__device__ __forceinline__ void split_pair(float x, float y, uint32_t &hi, uint32_t &lo){
    __nv_bfloat162 hv = __floats2bfloat162_rn(x, y);
    hi = *reinterpret_cast<uint32_t*>(&hv);
    float rx = x - __low2float(hv);
    float ry = y - __high2float(hv);
    __nv_bfloat162 lv = __floats2bfloat162_rn(rx, ry);
    lo = *reinterpret_cast<uint32_t*>(&lv);
}

__device__ __forceinline__ void mma16(float* c, const uint32_t* a, uint32_t b0, uint32_t b1){
    asm volatile("mma.sync.aligned.m16n8k16.row.col.f32.bf16.bf16.f32 "
        "{%0,%1,%2,%3},{%4,%5,%6,%7},{%8,%9},{%0,%1,%2,%3};"
        : "+f"(c[0]),"+f"(c[1]),"+f"(c[2]),"+f"(c[3])
        : "r"(a[0]),"r"(a[1]),"r"(a[2]),"r"(a[3]),"r"(b0),"r"(b1));
}

__device__ __forceinline__ void cp16(uint32_t saddr, const void* gptr){
    asm volatile("cp.async.cg.shared.global [%0], [%1], 16;" :: "r"(saddr), "l"(gptr));
}

// ================= split-bf16 tensor GEMM: C = A(MxK) @ W(KxN) + bias =======
// Block tile 128x64, BK=32, 256 threads = 8 warps (2m x 4n), warp tile 64x16.
// 2 CTAs/SM. Smem/buffer (u32): Ah[128][20] Al[128][20] Bh[16][68] Bl[16][68]
#define GBUF 7296
#define GEMM_SMEM (2*GBUF*4)   // 58368 B

__global__ void __launch_bounds__(256, 2) gemm_bf3(
    const float* __restrict__ A, const float* __restrict__ W,
    const float* __restrict__ bias, float* __restrict__ out,
    int M, int K, int N, int heads_mode, int S_rows, int L, int s_off)
{
    extern __shared__ uint32_t sm[];
    const int tid = threadIdx.x, lane = tid & 31, wrp = tid >> 5;
    const int g = lane >> 2, t = lane & 3;
    const int wm = wrp >> 2, wn = wrp & 3;
    const int row0 = blockIdx.y * 128, col0 = blockIdx.x * 64;

    float acc[4][2][4];
    #pragma unroll
    for (int i=0;i<4;i++)
        #pragma unroll
        for (int j=0;j<2;j++)
            #pragma unroll
            for (int r=0;r<4;r++) acc[i][j][r]=0.f;

    const int am  = tid >> 3;      // A row (+i*32)
    const int ak4 = tid & 7;       // A k4
    const int bk2 = tid >> 4;      // B k2 (0..15)
    const int bn4 = tid & 15;      // B n4 (0..15)

    float4 ra[4], rb0, rb1;
    const int nT = K >> 5;

#define LOADG(tk) { \
    const float* Ab = A + (size_t)row0 * K + (tk)*32; \
    _Pragma("unroll") \
    for (int i=0;i<4;i++) ra[i] = *(const float4*)&Ab[(size_t)(am + i*32)*K + ak4*4]; \
    const float* Wb = W + (size_t)((tk)*32) * N + col0; \
    rb0 = *(const float4*)&Wb[(size_t)(2*bk2)*N + bn4*4]; \
    rb1 = *(const float4*)&Wb[(size_t)(2*bk2+1)*N + bn4*4]; }

#define STOREB(buf) { \
    uint32_t* Ah = (buf); uint32_t* Al = (buf)+2560; \
    uint32_t* Bh = (buf)+5120; uint32_t* Bl = (buf)+6208; \
    _Pragma("unroll") \
    for (int i=0;i<4;i++){ \
        int m = am + i*32; \
        uint2 hv, lv; \
        split_pair(ra[i].x, ra[i].y, hv.x, lv.x); \
        split_pair(ra[i].z, ra[i].w, hv.y, lv.y); \
        int o = m*20 + ak4*2; \
        *(uint2*)&Ah[o] = hv; *(uint2*)&Al[o] = lv; \
    } \
    { \
        uint4 hv, lv; \
        split_pair(rb0.x, rb1.x, hv.x, lv.x); \
        split_pair(rb0.y, rb1.y, hv.y, lv.y); \
        split_pair(rb0.z, rb1.z, hv.z, lv.z); \
        split_pair(rb0.w, rb1.w, hv.w, lv.w); \
        int o = bk2*68 + bn4*4; \
        *(uint4*)&Bh[o] = hv; *(uint4*)&Bl[o] = lv; \
    } }

    LOADG(0);
    STOREB(sm);
    __syncthreads();

    for (int tk=0; tk<nT; tk++){
        uint32_t* buf = sm + (tk&1)*GBUF;
        if (tk+1 < nT) LOADG(tk+1);
        const uint32_t* Ah = buf;        const uint32_t* Al = buf+2560;
        const uint32_t* Bh = buf+5120;   const uint32_t* Bl = buf+6208;
        #pragma unroll
        for (int s=0;s<2;s++){
            uint32_t ah[4][4], al[4][4], bh[2][2], bl[2][2];
            #pragma unroll
            for (int mt=0;mt<4;mt++){
                int base = (wm*64 + mt*16 + g)*20 + s*8 + t;
                ah[mt][0]=Ah[base];     ah[mt][1]=Ah[base+160];
                ah[mt][2]=Ah[base+4];   ah[mt][3]=Ah[base+164];
                al[mt][0]=Al[base];     al[mt][1]=Al[base+160];
                al[mt][2]=Al[base+4];   al[mt][3]=Al[base+164];
            }
            #pragma unroll
            for (int nt=0;nt<2;nt++){
                int base = (s*8+t)*68 + wn*16 + nt*8 + g;
                bh[nt][0]=Bh[base]; bh[nt][1]=Bh[base+272];
                bl[nt][0]=Bl[base]; bl[nt][1]=Bl[base+272];
            }
            #pragma unroll
            for (int mt=0;mt<4;mt++)
                #pragma unroll
                for (int nt=0;nt<2;nt++){
                    mma16(acc[mt][nt], ah[mt], bh[nt][0], bh[nt][1]);
                    mma16(acc[mt][nt], ah[mt], bl[nt][0], bl[nt][1]);
                    mma16(acc[mt][nt], al[mt], bh[nt][0], bh[nt][1]);
                }
        }
        if (tk+1 < nT) { STOREB(sm + ((tk+1)&1)*GBUF); }
        __syncthreads();
    }

    #pragma unroll
    for (int mt=0;mt<4;mt++){
        int m0r = row0 + wm*64 + mt*16 + g;
        #pragma unroll
        for (int nt=0;nt<2;nt++){
            int c = col0 + wn*16 + nt*8 + t*2;
            float b0v = bias[c], b1v = bias[c+1];
            float2 v0 = make_float2(acc[mt][nt][0]+b0v, acc[mt][nt][1]+b1v);
            float2 v1 = make_float2(acc[mt][nt][2]+b0v, acc[mt][nt][3]+b1v);
            if (!heads_mode){
                *(float2*)&out[(size_t)m0r*N + c]     = v0;
                *(float2*)&out[(size_t)(m0r+8)*N + c] = v1;
            } else {
                int hh = c >> 6, hd = c & 63;
                int bb = m0r / S_rows, ss = m0r - bb*S_rows;
                *(float2*)&out[((size_t)(bb*NUM_H+hh)*L + s_off + ss)*64 + hd] = v0;
                int m1r = m0r + 8;
                int bb1 = m1r / S_rows, ss1 = m1r - bb1*S_rows;
                *(float2*)&out[((size_t)(bb1*NUM_H+hh)*L + s_off + ss1)*64 + hd] = v1;
            }
        }
    }
#undef LOADG
#undef STOREB
}

// ---------------- per-(b,h,d) mean/std over s=0..1023 (ddof=1) ----------------
__global__ void stats_kernel(const float* __restrict__ buf, int L,
                             float* __restrict__ mean, float* __restrict__ stdev)
{
    const int bh = blockIdx.x;
    const int tx = threadIdx.x & 63;
    const int ty = threadIdx.x >> 6;
    const float* p = buf + (size_t)bh * L * 64;
    float s = 0.f, ss = 0.f;
    for (int i = ty; i < 1024; i += 4) {
        float v = p[(size_t)i*64 + tx];
        s += v; ss += v*v;
    }
    __shared__ float sh1[4][64], sh2[4][64];
    sh1[ty][tx] = s; sh2[ty][tx] = ss;
    __syncthreads();
    if (ty == 0) {
        s  = sh1[0][tx]+sh1[1][tx]+sh1[2][tx]+sh1[3][tx];
        ss = sh2[0][tx]+sh2[1][tx]+sh2[2][tx]+sh2[3][tx];
        float m = s * (1.0f/1024.0f);
        float var = (ss - 1024.0f*m*m) * (1.0f/1023.0f);
        mean[bh*64+tx]  = m;
        stdev[bh*64+tx] = sqrtf(var + 1e-5f);
    }
}

// ---------------- AdaIN apply (b in {1,3}) + KV replication ----------------
__global__ void adain_apply_kernel(
    float* __restrict__ q, float* __restrict__ k, float* __restrict__ v,
    const float* __restrict__ mq, const float* __restrict__ sq,
    const float* __restrict__ mk, const float* __restrict__ sk)
{
    const int idx = blockIdx.x * 256 + threadIdx.x;
    if (idx >= 4*24*1024*16) return;
    const int c  = (idx & 15) * 4;
    const int s  = (idx >> 4) & 1023;
    const int bh = idx >> 14;
    const int b  = bh / 24;
    const int h  = bh - b*24;
    const int src = (b >= 2) ? 2 : 0;
    const int sbh = src*24 + h;

    const size_t ksrc = ((size_t)sbh*LK + s)*64 + c;
    const size_t kdst = ((size_t)bh*LK + 1024 + s)*64 + c;
    float4 kr = *(const float4*)&k[ksrc];
    float4 vr = *(const float4*)&v[ksrc];
    *(float4*)&k[kdst] = kr;
    *(float4*)&v[kdst] = vr;

    if (b & 1) {
        const int ib = bh*64 + c, is = sbh*64 + c;
        {
            float4 mb = *(const float4*)&mq[ib], sb = *(const float4*)&sq[ib];
            float4 ms = *(const float4*)&mq[is], so = *(const float4*)&sq[is];
            const size_t qi = ((size_t)bh*LQ + s)*64 + c;
            float4 x = *(const float4*)&q[qi];
            x.x = (x.x - mb.x)/sb.x*so.x + ms.x;
            x.y = (x.y - mb.y)/sb.y*so.y + ms.y;
            x.z = (x.z - mb.z)/sb.z*so.z + ms.z;
            x.w = (x.w - mb.w)/sb.w*so.w + ms.w;
            *(float4*)&q[qi] = x;
        }
        {
            float4 mb = *(const float4*)&mk[ib], sb = *(const float4*)&sk[ib];
            float4 ms = *(const float4*)&mk[is], so = *(const float4*)&sk[is];
            const size_t ki = ((size_t)bh*LK + s)*64 + c;
            float4 x = *(const float4*)&k[ki];
            x.x = (x.x - mb.x)/sb.x*so.x + ms.x;
            x.y = (x.y - mb.y)/sb.y*so.y + ms.y;
            x.z = (x.z - mb.z)/sb.z*so.z + ms.z;
            x.w = (x.w - mb.w)/sb.w*so.w + ms.w;
            *(float4*)&k[ki] = x;
        }
    }
}

// ---------------- convert K/V to fragment-packed uint4 layout ----------------
__global__ void __launch_bounds__(256) convert_k(
    const float* __restrict__ k, uint4* __restrict__ kf)
{
    __shared__ float sK[64][65];
    const int tid = threadIdx.x;
    const int kt = blockIdx.x, bh = blockIdx.y;
    const float* src = k + ((size_t)bh*LK + kt*64)*64;
    #pragma unroll
    for (int i=0;i<16;i++){
        int e = tid + i*256;
        sK[e>>6][e&63] = src[e];
    }
    __syncthreads();
    uint4* dst = kf + ((size_t)bh*36 + kt)*1024;
    #pragma unroll
    for (int i=0;i<4;i++){
        int slot = tid + i*256;
        int lane = slot & 31, nt = (slot>>5)&7, s = slot>>8;
        int g = lane>>2, t = lane&3;
        int kv = nt*8+g, d0 = 16*s+2*t;
        uint4 w4;
        split_pair(sK[kv][d0],   sK[kv][d0+1], w4.x, w4.z);
        split_pair(sK[kv][d0+8], sK[kv][d0+9], w4.y, w4.w);
        dst[slot] = w4;
    }
}

__global__ void __launch_bounds__(256) convert_v(
    const float* __restrict__ v, uint4* __restrict__ vf)
{
    __shared__ float sV[64][65];
    const int tid = threadIdx.x;
    const int kt = blockIdx.x, bh = blockIdx.y;
    const float* src = v + ((size_t)bh*LK + kt*64)*64;
    #pragma unroll
    for (int i=0;i<16;i++){
        int e = tid + i*256;
        sV[e>>6][e&63] = src[e];
    }
    __syncthreads();
    uint4* dst = vf + ((size_t)bh*36 + kt)*1024;
    #pragma unroll
    for (int i=0;i<4;i++){
        int slot = tid + i*256;
        int lane = slot & 31, j = (slot>>5)&7, s2 = slot>>8;
        int g = lane>>2, t = lane&3;
        int d = j*8+g, r0 = 16*s2+2*t;
        uint4 w4;
        split_pair(sV[r0][d],   sV[r0+1][d], w4.x, w4.z);
        split_pair(sV[r0+8][d], sV[r0+9][d], w4.y, w4.w);
        dst[slot] = w4;
    }
}

// ================= split-bf16 flash attention, max-free softmax =============
#define AT_SMEM (2*2048*16)

__global__ void __launch_bounds__(256, 2) attn_bf3(
    const float* __restrict__ Q,
    const uint4* __restrict__ KF, const uint4* __restrict__ VF,
    float* __restrict__ outh, float* __restrict__ oute)
{
    extern __shared__ uint4 sm4[];
    const int tid = threadIdx.x, lane = tid & 31, w = tid >> 5;
    const int g = lane >> 2, t = lane & 3;
    const int qt = blockIdx.x, h = blockIdx.y, b = blockIdx.z;
    const size_t bh = (size_t)b*NUM_H + h;
    const float* Qg = Q + (bh*LQ + (size_t)qt*128) * 64;
    const uint4* Kg = KF + bh*36*1024;
    const uint4* Vg = VF + bh*36*1024;
    const uint32_t smem_base = (uint32_t)__cvta_generic_to_shared(sm4);
    const float QSCALE = 0.125f * 1.44269504088896f;

#define STAGE(kt_, buf_) { \
    uint32_t sb = smem_base + (buf_)*32768u; \
    const uint4* kp = Kg + (size_t)(kt_)*1024 + tid; \
    const uint4* vp = Vg + (size_t)(kt_)*1024 + tid; \
    _Pragma("unroll") \
    for (int i_=0;i_<4;i_++){ \
        cp16(sb + (uint32_t)(tid + i_*256)*16u,           kp + i_*256); \
        cp16(sb + 16384u + (uint32_t)(tid + i_*256)*16u,  vp + i_*256); \
    } \
    asm volatile("cp.async.commit_group;"); }

    STAGE(0, 0);

    uint32_t qh[4][4], ql[4][4];
    {
        const int r0 = w*16 + g;
        #pragma unroll
        for (int s=0;s<4;s++){
            int d0 = 16*s + 2*t;
            float2 x00 = *(const float2*)&Qg[(size_t)r0*64 + d0];
            float2 x10 = *(const float2*)&Qg[(size_t)(r0+8)*64 + d0];
            float2 x01 = *(const float2*)&Qg[(size_t)r0*64 + d0 + 8];
            float2 x11 = *(const float2*)&Qg[(size_t)(r0+8)*64 + d0 + 8];
            split_pair(x00.x*QSCALE, x00.y*QSCALE, qh[s][0], ql[s][0]);
            split_pair(x10.x*QSCALE, x10.y*QSCALE, qh[s][1], ql[s][1]);
            split_pair(x01.x*QSCALE, x01.y*QSCALE, qh[s][2], ql[s][2]);
            split_pair(x11.x*QSCALE, x11.y*QSCALE, qh[s][3], ql[s][3]);
        }
    }

    float o_[8][4];
    #pragma unroll
    for (int j=0;j<8;j++){ o_[j][0]=0.f; o_[j][1]=0.f; o_[j][2]=0.f; o_[j][3]=0.f; }
    float l0s=0.f, l1s=0.f;

    for (int kt=0; kt<36; kt++){
        asm volatile("cp.async.wait_group 0;");
        __syncthreads();
        if (kt+1 < 36) { STAGE(kt+1, (kt+1)&1); }

        const uint4* Kt = sm4 + (kt&1)*2048;
        const uint4* Vt = Kt + 1024;

        float s_[8][4];
        #pragma unroll
        for (int j=0;j<8;j++){ s_[j][0]=0.f; s_[j][1]=0.f; s_[j][2]=0.f; s_[j][3]=0.f; }
        #pragma unroll
        for (int s=0;s<4;s++)
            #pragma unroll
            for (int nt=0;nt<8;nt++){
                uint4 kw = Kt[(s*8+nt)*32 + lane];
                mma16(s_[nt], qh[s], kw.x, kw.y);
                mma16(s_[nt], qh[s], kw.z, kw.w);
                mma16(s_[nt], ql[s], kw.x, kw.y);
            }

        #pragma unroll
        for (int j=0;j<8;j++){
            s_[j][0]=exp2f(s_[j][0]); s_[j][1]=exp2f(s_[j][1]);
            s_[j][2]=exp2f(s_[j][2]); s_[j][3]=exp2f(s_[j][3]);
            l0s += s_[j][0]+s_[j][1];
            l1s += s_[j][2]+s_[j][3];
        }

        uint32_t ph[4][4], pl[4][4];
        #pragma unroll
        for (int s2=0;s2<4;s2++){
            split_pair(s_[2*s2][0],   s_[2*s2][1],   ph[s2][0], pl[s2][0]);
            split_pair(s_[2*s2][2],   s_[2*s2][3],   ph[s2][1], pl[s2][1]);
            split_pair(s_[2*s2+1][0], s_[2*s2+1][1], ph[s2][2], pl[s2][2]);
            split_pair(s_[2*s2+1][2], s_[2*s2+1][3], ph[s2][3], pl[s2][3]);
        }

        #pragma unroll
        for (int s2=0;s2<4;s2++)
            #pragma unroll
            for (int j=0;j<8;j++){
                uint4 vw = Vt[(s2*8+j)*32 + lane];
                mma16(o_[j], ph[s2], vw.x, vw.y);
                mma16(o_[j], ph[s2], vw.z, vw.w);
                mma16(o_[j], pl[s2], vw.x, vw.y);
            }
    }
#undef STAGE

    l0s += __shfl_xor_sync(0xffffffffu, l0s, 1);
    l0s += __shfl_xor_sync(0xffffffffu, l0s, 2);
    l1s += __shfl_xor_sync(0xffffffffu, l1s, 1);
    l1s += __shfl_xor_sync(0xffffffffu, l1s, 2);
    float inv0 = 1.0f / l0s, inv1 = 1.0f / l1s;
    int q0 = qt*128 + w*16 + g;
    #pragma unroll
    for (int j=0;j<8;j++){
        int c = h*64 + j*8 + t*2;
        float2 v0 = make_float2(o_[j][0]*inv0, o_[j][1]*inv0);
        float2 v1 = make_float2(o_[j][2]*inv1, o_[j][3]*inv1);
        if (q0 < 1024){
            *(float2*)&outh[((size_t)b*1024 + q0)*1536 + c]     = v0;
            *(float2*)&outh[((size_t)b*1024 + q0 + 8)*1536 + c] = v1;
        } else {
            *(float2*)&oute[((size_t)b*256 + q0-1024)*1536 + c]     = v0;
            *(float2*)&oute[((size_t)b*256 + q0-1024 + 8)*1536 + c] = v1;
        }
    }
}

// ---------------- launch ----------------
extern "C" void kernel_launch(void* const* d_in, const int* in_sizes, int n_in,
                              void* d_out, int out_size)
{
    (void)in_sizes; (void)n_in; (void)out_size;
    const float* hs  = (const float*)d_in[0];
    const float* ehs = (const float*)d_in[1];
    const float* wq  = (const float*)d_in[2];  const float* bq  = (const float*)d_in[3];
    const float* wk  = (const float*)d_in[4];  const float* bk  = (const float*)d_in[5];
    const float* wv  = (const float*)d_in[6];  const float* bv  = (const float*)d_in[7];
    const float* awq = (const float*)d_in[8];  const float* abq = (const float*)d_in[9];
    const float* awk = (const float*)d_in[10]; const float* abk = (const float*)d_in[11];
    const float* awv = (const float*)d_in[12]; const float* abv = (const float*)d_in[13];
    const float* wo  = (const float*)d_in[14]; const float* bo  = (const float*)d_in[15];
    const float* wao = (const float*)d_in[16]; const float* bao = (const float*)d_in[17];
    float* out = (float*)d_out;

    float *q, *k, *v, *ah, *ae, *mq, *sq, *mk, *sk;
    uint4 *kf, *vf;
    cudaGetSymbolAddress((void**)&q,  g_q);
    cudaGetSymbolAddress((void**)&k,  g_k);
    cudaGetSymbolAddress((void**)&v,  g_v);
    cudaGetSymbolAddress((void**)&ah, g_ah);
    cudaGetSymbolAddress((void**)&ae, g_ae);
    cudaGetSymbolAddress((void**)&mq, g_mq);
    cudaGetSymbolAddress((void**)&sq, g_sq);
    cudaGetSymbolAddress((void**)&mk, g_mk);
    cudaGetSymbolAddress((void**)&sk, g_sk);
    cudaGetSymbolAddress((void**)&kf, g_kf);
    cudaGetSymbolAddress((void**)&vf, g_vf);

    static int attr_set = 0;
    if (!attr_set) {
        cudaFuncSetAttribute(gemm_bf3, cudaFuncAttributeMaxDynamicSharedMemorySize, GEMM_SMEM);
        cudaFuncSetAttribute(attn_bf3, cudaFuncAttributeMaxDynamicSharedMemorySize, AT_SMEM);
        attr_set = 1;
    }

    const dim3 blk(256);
    const dim3 g1(24, 32);   // N/64 x M/128 for M=4096
    const dim3 g2(24, 8);    // M=1024

    gemm_bf3<<<g1, blk, GEMM_SMEM>>>(hs, wq, bq, q, 4096, 1536, 1536, 1, 1024, LQ, 0);
    gemm_bf3<<<g1, blk, GEMM_SMEM>>>(hs, wk, bk, k, 4096, 1536, 1536, 1, 1024, LK, 0);
    gemm_bf3<<<g1, blk, GEMM_SMEM>>>(hs, wv, bv, v, 4096, 1536, 1536, 1, 1024, LK, 0);
    gemm_bf3<<<g2, blk, GEMM_SMEM>>>(ehs, awq, abq, q, 1024, 1536, 1536, 1, 256, LQ, 1024);
    gemm_bf3<<<g2, blk, GEMM_SMEM>>>(ehs, awk, abk, k, 1024, 1536, 1536, 1, 256, LK, 2048);
    gemm_bf3<<<g2, blk, GEMM_SMEM>>>(ehs, awv, abv, v, 1024, 1536, 1536, 1, 256, LK, 2048);

    stats_kernel<<<96, 256>>>(q, LQ, mq, sq);
    stats_kernel<<<96, 256>>>(k, LK, mk, sk);
    adain_apply_kernel<<<6144, 256>>>(q, k, v, mq, sq, mk, sk);

    convert_k<<<dim3(36, 96), blk>>>(k, kf);
    convert_v<<<dim3(36, 96), blk>>>(v, vf);

    attn_bf3<<<dim3(10, 24, 4), blk, AT_SMEM>>>(q, kf, vf, ah, ae);

    gemm_bf3<<<g1, blk, GEMM_SMEM>>>(ah, wo,  bo,  out,                     4096, 1536, 1536, 0, 0, 0, 0);
    gemm_bf3<<<g2, blk, GEMM_SMEM>>>(ae, wao, bao, out + (size_t)4096*1536, 1024, 1536, 1536, 0, 0, 0, 0);
}

// round 8
// speedup vs baseline: 1.1764x; 1.1764x over previous
#include <cuda_runtime.h>
#include <cuda_bf16.h>
#include <math.h>
#include <stdint.h>

#define NUM_H 24
#define LQ 1280
#define LK 2304

// ---------------- scratch (device globals; no allocations) ----------------
__device__ float g_q[4*24*1280*64];      // (B,H,LQ,64)
__device__ float g_k[4*24*2304*64];      // (B,H,LK,64)
__device__ float g_v[4*24*2304*64];
__device__ float g_ah[4*1024*1536];      // attention out, hidden part (B,S,D)
__device__ float g_ae[4*256*1536];       // attention out, encoder part (B,SE,D)
__device__ float g_mq[6144], g_sq[6144], g_mk[6144], g_sk[6144];
// fragment-packed K/V for attention
__device__ uint4 g_kf[96*36*1024];
__device__ uint4 g_vf[96*36*1024];

// ---------------- bf16 helpers ----------------
__device__ __forceinline__ void split_pair(float x, float y, uint32_t &hi, uint32_t &lo){
    __nv_bfloat162 hv = __floats2bfloat162_rn(x, y);
    hi = *reinterpret_cast<uint32_t*>(&hv);
    float rx = x - __low2float(hv);
    float ry = y - __high2float(hv);
    __nv_bfloat162 lv = __floats2bfloat162_rn(rx, ry);
    lo = *reinterpret_cast<uint32_t*>(&lv);
}

__device__ __forceinline__ void mma16(float* c, const uint32_t* a, uint32_t b0, uint32_t b1){
    asm volatile("mma.sync.aligned.m16n8k16.row.col.f32.bf16.bf16.f32 "
        "{%0,%1,%2,%3},{%4,%5,%6,%7},{%8,%9},{%0,%1,%2,%3};"
        : "+f"(c[0]),"+f"(c[1]),"+f"(c[2]),"+f"(c[3])
        : "r"(a[0]),"r"(a[1]),"r"(a[2]),"r"(a[3]),"r"(b0),"r"(b1));
}

__device__ __forceinline__ void cp16(uint32_t saddr, const void* gptr){
    asm volatile("cp.async.cg.shared.global [%0], [%1], 16;" :: "r"(saddr), "l"(gptr));
}

// ================= split-bf16 GEMM core: 128x128 tile, BK=32, 512 threads ====
// 16 warps as 4m x 4n, warp tile 32x32.
// Smem per buffer (u32): Ah[128][20] Al[128][20] Bh[16][136] Bl[16][136]
#define GBUF 9472
#define GEMM_SMEM (2*GBUF*4)   // 75776 B

__device__ __forceinline__ void gemm_core(
    const float* __restrict__ A, const float* __restrict__ W,
    const float* __restrict__ bias, float* __restrict__ out,
    int K, int N, int heads_mode, int S_rows, int L, int s_off,
    int row0, int col0, uint32_t* sm)
{
    const int tid = threadIdx.x, lane = tid & 31, wrp = tid >> 5;
    const int g = lane >> 2, t = lane & 3;
    const int wm = wrp >> 2, wn = wrp & 3;

    float acc[2][4][4];
    #pragma unroll
    for (int i=0;i<2;i++)
        #pragma unroll
        for (int j=0;j<4;j++)
            #pragma unroll
            for (int r=0;r<4;r++) acc[i][j][r]=0.f;

    const int am0 = tid >> 3;      // 0..63 (+64 for second)
    const int ak4 = tid & 7;
    const int bk2 = tid >> 5;      // 0..15
    const int bn4 = tid & 31;

    float4 ra[2], rb0, rb1;
    const int nT = K >> 5;

#define LOADG(tk) { \
    const float* Ab = A + (size_t)row0 * K + (tk)*32; \
    ra[0] = *(const float4*)&Ab[(size_t)am0*K + ak4*4]; \
    ra[1] = *(const float4*)&Ab[(size_t)(am0+64)*K + ak4*4]; \
    const float* Wb = W + (size_t)((tk)*32) * N + col0; \
    rb0 = *(const float4*)&Wb[(size_t)(2*bk2)*N + bn4*4]; \
    rb1 = *(const float4*)&Wb[(size_t)(2*bk2+1)*N + bn4*4]; }

#define STOREB(buf) { \
    uint32_t* Ah = (buf); uint32_t* Al = (buf)+2560; \
    uint32_t* Bh = (buf)+5120; uint32_t* Bl = (buf)+7296; \
    _Pragma("unroll") \
    for (int i=0;i<2;i++){ \
        uint2 hv, lv; \
        split_pair(ra[i].x, ra[i].y, hv.x, lv.x); \
        split_pair(ra[i].z, ra[i].w, hv.y, lv.y); \
        int o = (am0 + i*64)*20 + ak4*2; \
        *(uint2*)&Ah[o] = hv; *(uint2*)&Al[o] = lv; \
    } \
    { \
        uint4 hv, lv; \
        split_pair(rb0.x, rb1.x, hv.x, lv.x); \
        split_pair(rb0.y, rb1.y, hv.y, lv.y); \
        split_pair(rb0.z, rb1.z, hv.z, lv.z); \
        split_pair(rb0.w, rb1.w, hv.w, lv.w); \
        int o = bk2*136 + bn4*4; \
        *(uint4*)&Bh[o] = hv; *(uint4*)&Bl[o] = lv; \
    } }

    LOADG(0);
    STOREB(sm);
    __syncthreads();

    for (int tk=0; tk<nT; tk++){
        uint32_t* buf = sm + (tk&1)*GBUF;
        if (tk+1 < nT) LOADG(tk+1);
        const uint32_t* Ah = buf;        const uint32_t* Al = buf+2560;
        const uint32_t* Bh = buf+5120;   const uint32_t* Bl = buf+7296;
        #pragma unroll
        for (int s=0;s<2;s++){
            uint32_t ah[2][4], al[2][4], bh[4][2], bl[4][2];
            #pragma unroll
            for (int mt=0;mt<2;mt++){
                int base = (wm*32 + mt*16 + g)*20 + s*8 + t;
                ah[mt][0]=Ah[base];     ah[mt][1]=Ah[base+160];
                ah[mt][2]=Ah[base+4];   ah[mt][3]=Ah[base+164];
                al[mt][0]=Al[base];     al[mt][1]=Al[base+160];
                al[mt][2]=Al[base+4];   al[mt][3]=Al[base+164];
            }
            #pragma unroll
            for (int nt=0;nt<4;nt++){
                int base = (s*8+t)*136 + wn*32 + nt*8 + g;
                bh[nt][0]=Bh[base]; bh[nt][1]=Bh[base+544];
                bl[nt][0]=Bl[base]; bl[nt][1]=Bl[base+544];
            }
            #pragma unroll
            for (int mt=0;mt<2;mt++)
                #pragma unroll
                for (int nt=0;nt<4;nt++){
                    mma16(acc[mt][nt], ah[mt], bh[nt][0], bh[nt][1]);
                    mma16(acc[mt][nt], ah[mt], bl[nt][0], bl[nt][1]);
                    mma16(acc[mt][nt], al[mt], bh[nt][0], bh[nt][1]);
                }
        }
        if (tk+1 < nT) { STOREB(sm + ((tk+1)&1)*GBUF); }
        __syncthreads();
    }

    #pragma unroll
    for (int mt=0;mt<2;mt++){
        int m0r = row0 + wm*32 + mt*16 + g;
        #pragma unroll
        for (int nt=0;nt<4;nt++){
            int c = col0 + wn*32 + nt*8 + t*2;
            float b0v = bias[c], b1v = bias[c+1];
            float2 v0 = make_float2(acc[mt][nt][0]+b0v, acc[mt][nt][1]+b1v);
            float2 v1 = make_float2(acc[mt][nt][2]+b0v, acc[mt][nt][3]+b1v);
            if (!heads_mode){
                *(float2*)&out[(size_t)m0r*N + c]     = v0;
                *(float2*)&out[(size_t)(m0r+8)*N + c] = v1;
            } else {
                int hh = c >> 6, hd = c & 63;
                int bb = m0r / S_rows, ss = m0r - bb*S_rows;
                *(float2*)&out[((size_t)(bb*NUM_H+hh)*L + s_off + ss)*64 + hd] = v0;
                int m1r = m0r + 8;
                int bb1 = m1r / S_rows, ss1 = m1r - bb1*S_rows;
                *(float2*)&out[((size_t)(bb1*NUM_H+hh)*L + s_off + ss1)*64 + hd] = v1;
            }
        }
    }
#undef LOADG
#undef STOREB
}

// fused QKV projection: blockIdx.z selects weight/bias/output/offsets
__global__ void __launch_bounds__(512, 1) gemm_qkv(
    const float* __restrict__ A,
    const float* __restrict__ W0, const float* __restrict__ W1, const float* __restrict__ W2,
    const float* __restrict__ b0, const float* __restrict__ b1, const float* __restrict__ b2,
    float* __restrict__ o0, float* __restrict__ o1, float* __restrict__ o2,
    int K, int N, int S_rows, int L0, int L1, int L2,
    int soff0, int soff1, int soff2)
{
    extern __shared__ uint32_t sm[];
    const int z = blockIdx.z;
    const float* W = (z==0)? W0 : (z==1)? W1 : W2;
    const float* bi = (z==0)? b0 : (z==1)? b1 : b2;
    float* out = (z==0)? o0 : (z==1)? o1 : o2;
    int L = (z==0)? L0 : (z==1)? L1 : L2;
    int soff = (z==0)? soff0 : (z==1)? soff1 : soff2;
    gemm_core(A, W, bi, out, K, N, 1, S_rows, L, soff,
              blockIdx.y*128, blockIdx.x*128, sm);
}

// fused output projection: z=0 hidden (M=4096), z=1 encoder (M=1024)
__global__ void __launch_bounds__(512, 1) gemm_out(
    const float* __restrict__ A0, const float* __restrict__ A1,
    const float* __restrict__ W0, const float* __restrict__ W1,
    const float* __restrict__ b0, const float* __restrict__ b1,
    float* __restrict__ o0, float* __restrict__ o1,
    int K, int N)
{
    extern __shared__ uint32_t sm[];
    const int z = blockIdx.z;
    if (z == 1 && blockIdx.y >= 8) return;
    const float* A = (z==0)? A0 : A1;
    const float* W = (z==0)? W0 : W1;
    const float* bi = (z==0)? b0 : b1;
    float* out = (z==0)? o0 : o1;
    gemm_core(A, W, bi, out, K, N, 0, 0, 0, 0,
              blockIdx.y*128, blockIdx.x*128, sm);
}

// ---------------- per-(b,h,d) mean/std over s=0..1023 (ddof=1) ----------------
__global__ void stats_kernel(const float* __restrict__ buf, int L,
                             float* __restrict__ mean, float* __restrict__ stdev)
{
    const int bh = blockIdx.x;
    const int tx = threadIdx.x & 63;
    const int ty = threadIdx.x >> 6;
    const float* p = buf + (size_t)bh * L * 64;
    float s = 0.f, ss = 0.f;
    for (int i = ty; i < 1024; i += 4) {
        float v = p[(size_t)i*64 + tx];
        s += v; ss += v*v;
    }
    __shared__ float sh1[4][64], sh2[4][64];
    sh1[ty][tx] = s; sh2[ty][tx] = ss;
    __syncthreads();
    if (ty == 0) {
        s  = sh1[0][tx]+sh1[1][tx]+sh1[2][tx]+sh1[3][tx];
        ss = sh2[0][tx]+sh2[1][tx]+sh2[2][tx]+sh2[3][tx];
        float m = s * (1.0f/1024.0f);
        float var = (ss - 1024.0f*m*m) * (1.0f/1023.0f);
        mean[bh*64+tx]  = m;
        stdev[bh*64+tx] = sqrtf(var + 1e-5f);
    }
}

// ---------------- AdaIN apply (b in {1,3}) + KV replication ----------------
__global__ void adain_apply_kernel(
    float* __restrict__ q, float* __restrict__ k, float* __restrict__ v,
    const float* __restrict__ mq, const float* __restrict__ sq,
    const float* __restrict__ mk, const float* __restrict__ sk)
{
    const int idx = blockIdx.x * 256 + threadIdx.x;
    if (idx >= 4*24*1024*16) return;
    const int c  = (idx & 15) * 4;
    const int s  = (idx >> 4) & 1023;
    const int bh = idx >> 14;
    const int b  = bh / 24;
    const int h  = bh - b*24;
    const int src = (b >= 2) ? 2 : 0;
    const int sbh = src*24 + h;

    const size_t ksrc = ((size_t)sbh*LK + s)*64 + c;
    const size_t kdst = ((size_t)bh*LK + 1024 + s)*64 + c;
    float4 kr = *(const float4*)&k[ksrc];
    float4 vr = *(const float4*)&v[ksrc];
    *(float4*)&k[kdst] = kr;
    *(float4*)&v[kdst] = vr;

    if (b & 1) {
        const int ib = bh*64 + c, is = sbh*64 + c;
        {
            float4 mb = *(const float4*)&mq[ib], sb = *(const float4*)&sq[ib];
            float4 ms = *(const float4*)&mq[is], so = *(const float4*)&sq[is];
            const size_t qi = ((size_t)bh*LQ + s)*64 + c;
            float4 x = *(const float4*)&q[qi];
            x.x = (x.x - mb.x)/sb.x*so.x + ms.x;
            x.y = (x.y - mb.y)/sb.y*so.y + ms.y;
            x.z = (x.z - mb.z)/sb.z*so.z + ms.z;
            x.w = (x.w - mb.w)/sb.w*so.w + ms.w;
            *(float4*)&q[qi] = x;
        }
        {
            float4 mb = *(const float4*)&mk[ib], sb = *(const float4*)&sk[ib];
            float4 ms = *(const float4*)&mk[is], so = *(const float4*)&sk[is];
            const size_t ki = ((size_t)bh*LK + s)*64 + c;
            float4 x = *(const float4*)&k[ki];
            x.x = (x.x - mb.x)/sb.x*so.x + ms.x;
            x.y = (x.y - mb.y)/sb.y*so.y + ms.y;
            x.z = (x.z - mb.z)/sb.z*so.z + ms.z;
            x.w = (x.w - mb.w)/sb.w*so.w + ms.w;
            *(float4*)&k[ki] = x;
        }
    }
}

// ---------------- convert K/V to fragment-packed uint4 layout ----------------
__global__ void __launch_bounds__(256) convert_k(
    const float* __restrict__ k, uint4* __restrict__ kf)
{
    __shared__ float sK[64][65];
    const int tid = threadIdx.x;
    const int kt = blockIdx.x, bh = blockIdx.y;
    const float* src = k + ((size_t)bh*LK + kt*64)*64;
    #pragma unroll
    for (int i=0;i<16;i++){
        int e = tid + i*256;
        sK[e>>6][e&63] = src[e];
    }
    __syncthreads();
    uint4* dst = kf + ((size_t)bh*36 + kt)*1024;
    #pragma unroll
    for (int i=0;i<4;i++){
        int slot = tid + i*256;
        int lane = slot & 31, nt = (slot>>5)&7, s = slot>>8;
        int g = lane>>2, t = lane&3;
        int kv = nt*8+g, d0 = 16*s+2*t;
        uint4 w4;
        split_pair(sK[kv][d0],   sK[kv][d0+1], w4.x, w4.z);
        split_pair(sK[kv][d0+8], sK[kv][d0+9], w4.y, w4.w);
        dst[slot] = w4;
    }
}

__global__ void __launch_bounds__(256) convert_v(
    const float* __restrict__ v, uint4* __restrict__ vf)
{
    __shared__ float sV[64][65];
    const int tid = threadIdx.x;
    const int kt = blockIdx.x, bh = blockIdx.y;
    const float* src = v + ((size_t)bh*LK + kt*64)*64;
    #pragma unroll
    for (int i=0;i<16;i++){
        int e = tid + i*256;
        sV[e>>6][e&63] = src[e];
    }
    __syncthreads();
    uint4* dst = vf + ((size_t)bh*36 + kt)*1024;
    #pragma unroll
    for (int i=0;i<4;i++){
        int slot = tid + i*256;
        int lane = slot & 31, j = (slot>>5)&7, s2 = slot>>8;
        int g = lane>>2, t = lane&3;
        int d = j*8+g, r0 = 16*s2+2*t;
        uint4 w4;
        split_pair(sV[r0][d],   sV[r0+1][d], w4.x, w4.z);
        split_pair(sV[r0+8][d], sV[r0+9][d], w4.y, w4.w);
        dst[slot] = w4;
    }
}

// ================= split-bf16 flash attention, max-free softmax =============
#define AT_SMEM (2*2048*16)

__global__ void __launch_bounds__(256, 2) attn_bf3(
    const float* __restrict__ Q,
    const uint4* __restrict__ KF, const uint4* __restrict__ VF,
    float* __restrict__ outh, float* __restrict__ oute)
{
    extern __shared__ uint4 sm4[];
    const int tid = threadIdx.x, lane = tid & 31, w = tid >> 5;
    const int g = lane >> 2, t = lane & 3;
    const int qt = blockIdx.x, h = blockIdx.y, b = blockIdx.z;
    const size_t bh = (size_t)b*NUM_H + h;
    const float* Qg = Q + (bh*LQ + (size_t)qt*128) * 64;
    const uint4* Kg = KF + bh*36*1024;
    const uint4* Vg = VF + bh*36*1024;
    const uint32_t smem_base = (uint32_t)__cvta_generic_to_shared(sm4);
    const float QSCALE = 0.125f * 1.44269504088896f;

#define STAGE(kt_, buf_) { \
    uint32_t sb = smem_base + (buf_)*32768u; \
    const uint4* kp = Kg + (size_t)(kt_)*1024 + tid; \
    const uint4* vp = Vg + (size_t)(kt_)*1024 + tid; \
    _Pragma("unroll") \
    for (int i_=0;i_<4;i_++){ \
        cp16(sb + (uint32_t)(tid + i_*256)*16u,           kp + i_*256); \
        cp16(sb + 16384u + (uint32_t)(tid + i_*256)*16u,  vp + i_*256); \
    } \
    asm volatile("cp.async.commit_group;"); }

    STAGE(0, 0);

    uint32_t qh[4][4], ql[4][4];
    {
        const int r0 = w*16 + g;
        #pragma unroll
        for (int s=0;s<4;s++){
            int d0 = 16*s + 2*t;
            float2 x00 = *(const float2*)&Qg[(size_t)r0*64 + d0];
            float2 x10 = *(const float2*)&Qg[(size_t)(r0+8)*64 + d0];
            float2 x01 = *(const float2*)&Qg[(size_t)r0*64 + d0 + 8];
            float2 x11 = *(const float2*)&Qg[(size_t)(r0+8)*64 + d0 + 8];
            split_pair(x00.x*QSCALE, x00.y*QSCALE, qh[s][0], ql[s][0]);
            split_pair(x10.x*QSCALE, x10.y*QSCALE, qh[s][1], ql[s][1]);
            split_pair(x01.x*QSCALE, x01.y*QSCALE, qh[s][2], ql[s][2]);
            split_pair(x11.x*QSCALE, x11.y*QSCALE, qh[s][3], ql[s][3]);
        }
    }

    float o_[8][4];
    #pragma unroll
    for (int j=0;j<8;j++){ o_[j][0]=0.f; o_[j][1]=0.f; o_[j][2]=0.f; o_[j][3]=0.f; }
    float l0s=0.f, l1s=0.f;

    for (int kt=0; kt<36; kt++){
        asm volatile("cp.async.wait_group 0;");
        __syncthreads();
        if (kt+1 < 36) { STAGE(kt+1, (kt+1)&1); }

        const uint4* Kt = sm4 + (kt&1)*2048;
        const uint4* Vt = Kt + 1024;

        float s_[8][4];
        #pragma unroll
        for (int j=0;j<8;j++){ s_[j][0]=0.f; s_[j][1]=0.f; s_[j][2]=0.f; s_[j][3]=0.f; }
        #pragma unroll
        for (int s=0;s<4;s++)
            #pragma unroll
            for (int nt=0;nt<8;nt++){
                uint4 kw = Kt[(s*8+nt)*32 + lane];
                mma16(s_[nt], qh[s], kw.x, kw.y);
                mma16(s_[nt], qh[s], kw.z, kw.w);
                mma16(s_[nt], ql[s], kw.x, kw.y);
            }

        #pragma unroll
        for (int j=0;j<8;j++){
            s_[j][0]=exp2f(s_[j][0]); s_[j][1]=exp2f(s_[j][1]);
            s_[j][2]=exp2f(s_[j][2]); s_[j][3]=exp2f(s_[j][3]);
            l0s += s_[j][0]+s_[j][1];
            l1s += s_[j][2]+s_[j][3];
        }

        uint32_t ph[4][4], pl[4][4];
        #pragma unroll
        for (int s2=0;s2<4;s2++){
            split_pair(s_[2*s2][0],   s_[2*s2][1],   ph[s2][0], pl[s2][0]);
            split_pair(s_[2*s2][2],   s_[2*s2][3],   ph[s2][1], pl[s2][1]);
            split_pair(s_[2*s2+1][0], s_[2*s2+1][1], ph[s2][2], pl[s2][2]);
            split_pair(s_[2*s2+1][2], s_[2*s2+1][3], ph[s2][3], pl[s2][3]);
        }

        #pragma unroll
        for (int s2=0;s2<4;s2++)
            #pragma unroll
            for (int j=0;j<8;j++){
                uint4 vw = Vt[(s2*8+j)*32 + lane];
                mma16(o_[j], ph[s2], vw.x, vw.y);
                mma16(o_[j], ph[s2], vw.z, vw.w);
                mma16(o_[j], pl[s2], vw.x, vw.y);
            }
    }
#undef STAGE

    l0s += __shfl_xor_sync(0xffffffffu, l0s, 1);
    l0s += __shfl_xor_sync(0xffffffffu, l0s, 2);
    l1s += __shfl_xor_sync(0xffffffffu, l1s, 1);
    l1s += __shfl_xor_sync(0xffffffffu, l1s, 2);
    float inv0 = 1.0f / l0s, inv1 = 1.0f / l1s;
    int q0 = qt*128 + w*16 + g;
    #pragma unroll
    for (int j=0;j<8;j++){
        int c = h*64 + j*8 + t*2;
        float2 v0 = make_float2(o_[j][0]*inv0, o_[j][1]*inv0);
        float2 v1 = make_float2(o_[j][2]*inv1, o_[j][3]*inv1);
        if (q0 < 1024){
            *(float2*)&outh[((size_t)b*1024 + q0)*1536 + c]     = v0;
            *(float2*)&outh[((size_t)b*1024 + q0 + 8)*1536 + c] = v1;
        } else {
            *(float2*)&oute[((size_t)b*256 + q0-1024)*1536 + c]     = v0;
            *(float2*)&oute[((size_t)b*256 + q0-1024 + 8)*1536 + c] = v1;
        }
    }
}

// ---------------- launch ----------------
extern "C" void kernel_launch(void* const* d_in, const int* in_sizes, int n_in,
                              void* d_out, int out_size)
{
    (void)in_sizes; (void)n_in; (void)out_size;
    const float* hs  = (const float*)d_in[0];
    const float* ehs = (const float*)d_in[1];
    const float* wq  = (const float*)d_in[2];  const float* bq  = (const float*)d_in[3];
    const float* wk  = (const float*)d_in[4];  const float* bk  = (const float*)d_in[5];
    const float* wv  = (const float*)d_in[6];  const float* bv  = (const float*)d_in[7];
    const float* awq = (const float*)d_in[8];  const float* abq = (const float*)d_in[9];
    const float* awk = (const float*)d_in[10]; const float* abk = (const float*)d_in[11];
    const float* awv = (const float*)d_in[12]; const float* abv = (const float*)d_in[13];
    const float* wo  = (const float*)d_in[14]; const float* bo  = (const float*)d_in[15];
    const float* wao = (const float*)d_in[16]; const float* bao = (const float*)d_in[17];
    float* out = (float*)d_out;

    float *q, *k, *v, *ah, *ae, *mq, *sq, *mk, *sk;
    uint4 *kf, *vf;
    cudaGetSymbolAddress((void**)&q,  g_q);
    cudaGetSymbolAddress((void**)&k,  g_k);
    cudaGetSymbolAddress((void**)&v,  g_v);
    cudaGetSymbolAddress((void**)&ah, g_ah);
    cudaGetSymbolAddress((void**)&ae, g_ae);
    cudaGetSymbolAddress((void**)&mq, g_mq);
    cudaGetSymbolAddress((void**)&sq, g_sq);
    cudaGetSymbolAddress((void**)&mk, g_mk);
    cudaGetSymbolAddress((void**)&sk, g_sk);
    cudaGetSymbolAddress((void**)&kf, g_kf);
    cudaGetSymbolAddress((void**)&vf, g_vf);

    static int attr_set = 0;
    if (!attr_set) {
        cudaFuncSetAttribute(gemm_qkv, cudaFuncAttributeMaxDynamicSharedMemorySize, GEMM_SMEM);
        cudaFuncSetAttribute(gemm_out, cudaFuncAttributeMaxDynamicSharedMemorySize, GEMM_SMEM);
        cudaFuncSetAttribute(attn_bf3, cudaFuncAttributeMaxDynamicSharedMemorySize, AT_SMEM);
        attr_set = 1;
    }

    // hidden QKV (fused over z): M=4096
    gemm_qkv<<<dim3(12, 32, 3), 512, GEMM_SMEM>>>(
        hs, wq, wk, wv, bq, bk, bv, q, k, v,
        1536, 1536, 1024, LQ, LK, LK, 0, 0, 0);
    // encoder QKV (fused over z): M=1024
    gemm_qkv<<<dim3(12, 8, 3), 512, GEMM_SMEM>>>(
        ehs, awq, awk, awv, abq, abk, abv, q, k, v,
        1536, 1536, 256, LQ, LK, LK, 1024, 2048, 2048);

    stats_kernel<<<96, 256>>>(q, LQ, mq, sq);
    stats_kernel<<<96, 256>>>(k, LK, mk, sk);
    adain_apply_kernel<<<6144, 256>>>(q, k, v, mq, sq, mk, sk);

    convert_k<<<dim3(36, 96), 256>>>(k, kf);
    convert_v<<<dim3(36, 96), 256>>>(v, vf);

    attn_bf3<<<dim3(10, 24, 4), 256, AT_SMEM>>>(q, kf, vf, ah, ae);

    // output projections (fused over z)
    gemm_out<<<dim3(12, 32, 2), 512, GEMM_SMEM>>>(
        ah, ae, wo, wao, bo, bao, out, out + (size_t)4096*1536, 1536, 1536);
}

// round 9
// speedup vs baseline: 1.2155x; 1.0332x over previous
#include <cuda_runtime.h>
#include <cuda_bf16.h>
#include <math.h>
#include <stdint.h>

#define NUM_H 24
#define LQ 1280
#define LK 2304

// ---------------- scratch (device globals; no allocations) ----------------
__device__ float g_q[4*24*1280*64];      // (B,H,LQ,64)
__device__ float g_k[4*24*2304*64];      // (B,H,LK,64)
__device__ float g_v[4*24*2304*64];
__device__ float g_ah[4*1024*1536];      // attention out, hidden part (B,S,D)
__device__ float g_ae[4*256*1536];       // attention out, encoder part (B,SE,D)
__device__ float g_mq[6144], g_sq[6144], g_mk[6144], g_sk[6144];
// fragment-packed K/V for attention
__device__ uint4 g_kf[96*36*1024];
__device__ uint4 g_vf[96*36*1024];

// ---------------- bf16 helpers ----------------
__device__ __forceinline__ void split_pair(float x, float y, uint32_t &hi, uint32_t &lo){
    __nv_bfloat162 hv = __floats2bfloat162_rn(x, y);
    hi = *reinterpret_cast<uint32_t*>(&hv);
    float rx = x - __low2float(hv);
    float ry = y - __high2float(hv);
    __nv_bfloat162 lv = __floats2bfloat162_rn(rx, ry);
    lo = *reinterpret_cast<uint32_t*>(&lv);
}

__device__ __forceinline__ void mma16(float* c, const uint32_t* a, uint32_t b0, uint32_t b1){
    asm volatile("mma.sync.aligned.m16n8k16.row.col.f32.bf16.bf16.f32 "
        "{%0,%1,%2,%3},{%4,%5,%6,%7},{%8,%9},{%0,%1,%2,%3};"
        : "+f"(c[0]),"+f"(c[1]),"+f"(c[2]),"+f"(c[3])
        : "r"(a[0]),"r"(a[1]),"r"(a[2]),"r"(a[3]),"r"(b0),"r"(b1));
}

__device__ __forceinline__ void ldsm4(uint32_t* r, uint32_t addr){
    asm volatile("ldmatrix.sync.aligned.m8n8.x4.shared.b16 {%0,%1,%2,%3}, [%4];"
        : "=r"(r[0]),"=r"(r[1]),"=r"(r[2]),"=r"(r[3]) : "r"(addr));
}

__device__ __forceinline__ void cp16(uint32_t saddr, const void* gptr){
    asm volatile("cp.async.cg.shared.global [%0], [%1], 16;" :: "r"(saddr), "l"(gptr));
}

// ================= split-bf16 GEMM: 128x128 tile, BK=32, 512 threads ========
// 16 warps as 4m x 4n, warp tile 32x32. A via ldmatrix, B via packed LDS.128.
// Buffer layout (u32): Ah[0,2048) rowmajor bf16 128x32 swizzled,
//                      Al[2048,4096), Bpk[4096,8192) = 1024 uint4 slots.
#define GBUF 8192
#define GEMM_SMEM (2*GBUF*4)   // 65536 B

__device__ __forceinline__ void gemm_core(
    const float* __restrict__ A, const float* __restrict__ W,
    const float* __restrict__ bias, float* __restrict__ out,
    int K, int N, int heads_mode, int S_rows, int L, int s_off,
    int row0, int col0, uint32_t* sm)
{
    const int tid = threadIdx.x, lane = tid & 31, wrp = tid >> 5;
    const int g = lane >> 2, t = lane & 3;
    const int wm = wrp >> 2, wn = wrp & 3;

    float acc[2][4][4];
    #pragma unroll
    for (int i=0;i<2;i++)
        #pragma unroll
        for (int j=0;j<4;j++)
            #pragma unroll
            for (int r=0;r<4;r++) acc[i][j][r]=0.f;

    // ---- staging maps ----
    const int am0 = tid >> 3;          // A row 0..63 (+64)
    const int ak4 = tid & 7;           // A k4 group
    const int bs  = tid >> 8;          // B s (0..1)
    const int bt  = (tid >> 6) & 3;    // B t (0..3)
    const int bn  = (tid & 63) * 2;    // B n (even)

    // ---- precomputed read offsets (bytes within buffer) ----
    const uint32_t sbase = (uint32_t)__cvta_generic_to_shared(sm);
    uint32_t a_off[2][2];   // [mt][s]
    #pragma unroll
    for (int mt=0; mt<2; mt++){
        int r = wm*32 + mt*16 + ((lane>>3)&1)*8 + (lane&7);
        int swz = (r>>1)&3;
        #pragma unroll
        for (int s=0; s<2; s++){
            int u = s*2 + (lane>>4);
            a_off[mt][s] = (uint32_t)(r*64 + ((u ^ swz)<<4));
        }
    }
    uint32_t b_slot[2][4];  // [s][nt] -> uint4 index within Bpk
    #pragma unroll
    for (int s=0; s<2; s++)
        #pragma unroll
        for (int nt=0; nt<4; nt++){
            int ntg = wn*4 + nt;
            int lp = ((g*4+t) ^ (g>>1)) ^ ((ntg&1)<<2);
            b_slot[s][nt] = (uint32_t)((s*16+ntg)*32 + lp);
        }

    float4 ra[2];
    float2 rb[4];
    const int nT = K >> 5;

#define LOADG(tk) { \
    const float* Ab = A + (size_t)row0 * K + (tk)*32; \
    ra[0] = *(const float4*)&Ab[(size_t)am0*K + ak4*4]; \
    ra[1] = *(const float4*)&Ab[(size_t)(am0+64)*K + ak4*4]; \
    const float* Wb = W + (size_t)((tk)*32 + bs*16 + 2*bt)*N + col0 + bn; \
    rb[0] = *(const float2*)Wb; \
    rb[1] = *(const float2*)(Wb + N); \
    rb[2] = *(const float2*)(Wb + 8*(size_t)N); \
    rb[3] = *(const float2*)(Wb + 9*(size_t)N); }

#define STOREB(buf) { \
    uint32_t* Ah = (buf); uint32_t* Al = (buf)+2048; \
    uint4* Bp = (uint4*)((buf)+4096); \
    _Pragma("unroll") \
    for (int i=0;i<2;i++){ \
        int r = am0 + i*64; \
        uint2 hv, lv; \
        split_pair(ra[i].x, ra[i].y, hv.x, lv.x); \
        split_pair(ra[i].z, ra[i].w, hv.y, lv.y); \
        int o = r*16 + (((ak4>>1) ^ ((r>>1)&3))<<2) + (ak4&1)*2; \
        *(uint2*)&Ah[o] = hv; *(uint2*)&Al[o] = lv; \
    } \
    { \
        uint4 w4; \
        split_pair(rb[0].x, rb[1].x, w4.x, w4.z); \
        split_pair(rb[2].x, rb[3].x, w4.y, w4.w); \
        int n0 = bn, ntg = n0>>3, gg = n0&7; \
        int lp = ((gg*4+bt) ^ (gg>>1)) ^ ((ntg&1)<<2); \
        Bp[(bs*16+ntg)*32 + lp] = w4; \
        split_pair(rb[0].y, rb[1].y, w4.x, w4.z); \
        split_pair(rb[2].y, rb[3].y, w4.y, w4.w); \
        int n1 = bn+1; ntg = n1>>3; gg = n1&7; \
        lp = ((gg*4+bt) ^ (gg>>1)) ^ ((ntg&1)<<2); \
        Bp[(bs*16+ntg)*32 + lp] = w4; \
    } }

    LOADG(0);
    STOREB(sm);
    __syncthreads();

    for (int tk=0; tk<nT; tk++){
        uint32_t* buf = sm + (tk&1)*GBUF;
        const uint32_t bufb = sbase + (uint32_t)(tk&1)*(GBUF*4);
        if (tk+1 < nT) LOADG(tk+1);
        const uint4* Bp = (const uint4*)(buf+4096);
        #pragma unroll
        for (int s=0;s<2;s++){
            uint32_t ah[2][4], al[2][4];
            #pragma unroll
            for (int mt=0;mt<2;mt++){
                ldsm4(ah[mt], bufb + a_off[mt][s]);
                ldsm4(al[mt], bufb + 8192u + a_off[mt][s]);
            }
            #pragma unroll
            for (int nt=0;nt<4;nt++){
                uint4 kw = Bp[b_slot[s][nt]];
                #pragma unroll
                for (int mt=0;mt<2;mt++){
                    mma16(acc[mt][nt], ah[mt], kw.x, kw.y);
                    mma16(acc[mt][nt], ah[mt], kw.z, kw.w);
                    mma16(acc[mt][nt], al[mt], kw.x, kw.y);
                }
            }
        }
        if (tk+1 < nT) { STOREB(sm + ((tk+1)&1)*GBUF); }
        __syncthreads();
    }

    #pragma unroll
    for (int mt=0;mt<2;mt++){
        int m0r = row0 + wm*32 + mt*16 + g;
        #pragma unroll
        for (int nt=0;nt<4;nt++){
            int c = col0 + wn*32 + nt*8 + t*2;
            float b0v = bias[c], b1v = bias[c+1];
            float2 v0 = make_float2(acc[mt][nt][0]+b0v, acc[mt][nt][1]+b1v);
            float2 v1 = make_float2(acc[mt][nt][2]+b0v, acc[mt][nt][3]+b1v);
            if (!heads_mode){
                *(float2*)&out[(size_t)m0r*N + c]     = v0;
                *(float2*)&out[(size_t)(m0r+8)*N + c] = v1;
            } else {
                int hh = c >> 6, hd = c & 63;
                int bb = m0r / S_rows, ss = m0r - bb*S_rows;
                *(float2*)&out[((size_t)(bb*NUM_H+hh)*L + s_off + ss)*64 + hd] = v0;
                int m1r = m0r + 8;
                int bb1 = m1r / S_rows, ss1 = m1r - bb1*S_rows;
                *(float2*)&out[((size_t)(bb1*NUM_H+hh)*L + s_off + ss1)*64 + hd] = v1;
            }
        }
    }
#undef LOADG
#undef STOREB
}

// fused QKV projection: blockIdx.z selects weight/bias/output/offsets
__global__ void __launch_bounds__(512, 1) gemm_qkv(
    const float* __restrict__ A,
    const float* __restrict__ W0, const float* __restrict__ W1, const float* __restrict__ W2,
    const float* __restrict__ b0, const float* __restrict__ b1, const float* __restrict__ b2,
    float* __restrict__ o0, float* __restrict__ o1, float* __restrict__ o2,
    int K, int N, int S_rows, int L0, int L1, int L2,
    int soff0, int soff1, int soff2)
{
    extern __shared__ uint32_t sm[];
    const int z = blockIdx.z;
    const float* W = (z==0)? W0 : (z==1)? W1 : W2;
    const float* bi = (z==0)? b0 : (z==1)? b1 : b2;
    float* out = (z==0)? o0 : (z==1)? o1 : o2;
    int L = (z==0)? L0 : (z==1)? L1 : L2;
    int soff = (z==0)? soff0 : (z==1)? soff1 : soff2;
    gemm_core(A, W, bi, out, K, N, 1, S_rows, L, soff,
              blockIdx.y*128, blockIdx.x*128, sm);
}

// fused output projection: z=0 hidden (M=4096), z=1 encoder (M=1024)
__global__ void __launch_bounds__(512, 1) gemm_out(
    const float* __restrict__ A0, const float* __restrict__ A1,
    const float* __restrict__ W0, const float* __restrict__ W1,
    const float* __restrict__ b0, const float* __restrict__ b1,
    float* __restrict__ o0, float* __restrict__ o1,
    int K, int N)
{
    extern __shared__ uint32_t sm[];
    const int z = blockIdx.z;
    if (z == 1 && blockIdx.y >= 8) return;
    const float* A = (z==0)? A0 : A1;
    const float* W = (z==0)? W0 : W1;
    const float* bi = (z==0)? b0 : b1;
    float* out = (z==0)? o0 : o1;
    gemm_core(A, W, bi, out, K, N, 0, 0, 0, 0,
              blockIdx.y*128, blockIdx.x*128, sm);
}

// ---------------- per-(b,h,d) mean/std over s=0..1023 (ddof=1) ----------------
__global__ void stats_kernel(const float* __restrict__ buf, int L,
                             float* __restrict__ mean, float* __restrict__ stdev)
{
    const int bh = blockIdx.x;
    const int tx = threadIdx.x & 63;
    const int ty = threadIdx.x >> 6;
    const float* p = buf + (size_t)bh * L * 64;
    float s = 0.f, ss = 0.f;
    for (int i = ty; i < 1024; i += 4) {
        float v = p[(size_t)i*64 + tx];
        s += v; ss += v*v;
    }
    __shared__ float sh1[4][64], sh2[4][64];
    sh1[ty][tx] = s; sh2[ty][tx] = ss;
    __syncthreads();
    if (ty == 0) {
        s  = sh1[0][tx]+sh1[1][tx]+sh1[2][tx]+sh1[3][tx];
        ss = sh2[0][tx]+sh2[1][tx]+sh2[2][tx]+sh2[3][tx];
        float m = s * (1.0f/1024.0f);
        float var = (ss - 1024.0f*m*m) * (1.0f/1023.0f);
        mean[bh*64+tx]  = m;
        stdev[bh*64+tx] = sqrtf(var + 1e-5f);
    }
}

// ---------------- AdaIN apply (b in {1,3}) + KV replication ----------------
__global__ void adain_apply_kernel(
    float* __restrict__ q, float* __restrict__ k, float* __restrict__ v,
    const float* __restrict__ mq, const float* __restrict__ sq,
    const float* __restrict__ mk, const float* __restrict__ sk)
{
    const int idx = blockIdx.x * 256 + threadIdx.x;
    if (idx >= 4*24*1024*16) return;
    const int c  = (idx & 15) * 4;
    const int s  = (idx >> 4) & 1023;
    const int bh = idx >> 14;
    const int b  = bh / 24;
    const int h  = bh - b*24;
    const int src = (b >= 2) ? 2 : 0;
    const int sbh = src*24 + h;

    const size_t ksrc = ((size_t)sbh*LK + s)*64 + c;
    const size_t kdst = ((size_t)bh*LK + 1024 + s)*64 + c;
    float4 kr = *(const float4*)&k[ksrc];
    float4 vr = *(const float4*)&v[ksrc];
    *(float4*)&k[kdst] = kr;
    *(float4*)&v[kdst] = vr;

    if (b & 1) {
        const int ib = bh*64 + c, is = sbh*64 + c;
        {
            float4 mb = *(const float4*)&mq[ib], sb = *(const float4*)&sq[ib];
            float4 ms = *(const float4*)&mq[is], so = *(const float4*)&sq[is];
            const size_t qi = ((size_t)bh*LQ + s)*64 + c;
            float4 x = *(const float4*)&q[qi];
            x.x = (x.x - mb.x)/sb.x*so.x + ms.x;
            x.y = (x.y - mb.y)/sb.y*so.y + ms.y;
            x.z = (x.z - mb.z)/sb.z*so.z + ms.z;
            x.w = (x.w - mb.w)/sb.w*so.w + ms.w;
            *(float4*)&q[qi] = x;
        }
        {
            float4 mb = *(const float4*)&mk[ib], sb = *(const float4*)&sk[ib];
            float4 ms = *(const float4*)&mk[is], so = *(const float4*)&sk[is];
            const size_t ki = ((size_t)bh*LK + s)*64 + c;
            float4 x = *(const float4*)&k[ki];
            x.x = (x.x - mb.x)/sb.x*so.x + ms.x;
            x.y = (x.y - mb.y)/sb.y*so.y + ms.y;
            x.z = (x.z - mb.z)/sb.z*so.z + ms.z;
            x.w = (x.w - mb.w)/sb.w*so.w + ms.w;
            *(float4*)&k[ki] = x;
        }
    }
}

// ---------------- convert K/V to fragment-packed uint4 layout ----------------
__global__ void __launch_bounds__(256) convert_k(
    const float* __restrict__ k, uint4* __restrict__ kf)
{
    __shared__ float sK[64][65];
    const int tid = threadIdx.x;
    const int kt = blockIdx.x, bh = blockIdx.y;
    const float* src = k + ((size_t)bh*LK + kt*64)*64;
    #pragma unroll
    for (int i=0;i<16;i++){
        int e = tid + i*256;
        sK[e>>6][e&63] = src[e];
    }
    __syncthreads();
    uint4* dst = kf + ((size_t)bh*36 + kt)*1024;
    #pragma unroll
    for (int i=0;i<4;i++){
        int slot = tid + i*256;
        int lane = slot & 31, nt = (slot>>5)&7, s = slot>>8;
        int g = lane>>2, t = lane&3;
        int kv = nt*8+g, d0 = 16*s+2*t;
        uint4 w4;
        split_pair(sK[kv][d0],   sK[kv][d0+1], w4.x, w4.z);
        split_pair(sK[kv][d0+8], sK[kv][d0+9], w4.y, w4.w);
        dst[slot] = w4;
    }
}

__global__ void __launch_bounds__(256) convert_v(
    const float* __restrict__ v, uint4* __restrict__ vf)
{
    __shared__ float sV[64][65];
    const int tid = threadIdx.x;
    const int kt = blockIdx.x, bh = blockIdx.y;
    const float* src = v + ((size_t)bh*LK + kt*64)*64;
    #pragma unroll
    for (int i=0;i<16;i++){
        int e = tid + i*256;
        sV[e>>6][e&63] = src[e];
    }
    __syncthreads();
    uint4* dst = vf + ((size_t)bh*36 + kt)*1024;
    #pragma unroll
    for (int i=0;i<4;i++){
        int slot = tid + i*256;
        int lane = slot & 31, j = (slot>>5)&7, s2 = slot>>8;
        int g = lane>>2, t = lane&3;
        int d = j*8+g, r0 = 16*s2+2*t;
        uint4 w4;
        split_pair(sV[r0][d],   sV[r0+1][d], w4.x, w4.z);
        split_pair(sV[r0+8][d], sV[r0+9][d], w4.y, w4.w);
        dst[slot] = w4;
    }
}

// ================= split-bf16 flash attention, max-free softmax =============
#define AT_SMEM (2*2048*16)

__global__ void __launch_bounds__(256, 2) attn_bf3(
    const float* __restrict__ Q,
    const uint4* __restrict__ KF, const uint4* __restrict__ VF,
    float* __restrict__ outh, float* __restrict__ oute)
{
    extern __shared__ uint4 sm4[];
    const int tid = threadIdx.x, lane = tid & 31, w = tid >> 5;
    const int g = lane >> 2, t = lane & 3;
    const int qt = blockIdx.x, h = blockIdx.y, b = blockIdx.z;
    const size_t bh = (size_t)b*NUM_H + h;
    const float* Qg = Q + (bh*LQ + (size_t)qt*128) * 64;
    const uint4* Kg = KF + bh*36*1024;
    const uint4* Vg = VF + bh*36*1024;
    const uint32_t smem_base = (uint32_t)__cvta_generic_to_shared(sm4);
    const float QSCALE = 0.125f * 1.44269504088896f;

#define STAGE(kt_, buf_) { \
    uint32_t sb = smem_base + (buf_)*32768u; \
    const uint4* kp = Kg + (size_t)(kt_)*1024 + tid; \
    const uint4* vp = Vg + (size_t)(kt_)*1024 + tid; \
    _Pragma("unroll") \
    for (int i_=0;i_<4;i_++){ \
        cp16(sb + (uint32_t)(tid + i_*256)*16u,           kp + i_*256); \
        cp16(sb + 16384u + (uint32_t)(tid + i_*256)*16u,  vp + i_*256); \
    } \
    asm volatile("cp.async.commit_group;"); }

    STAGE(0, 0);

    uint32_t qh[4][4], ql[4][4];
    {
        const int r0 = w*16 + g;
        #pragma unroll
        for (int s=0;s<4;s++){
            int d0 = 16*s + 2*t;
            float2 x00 = *(const float2*)&Qg[(size_t)r0*64 + d0];
            float2 x10 = *(const float2*)&Qg[(size_t)(r0+8)*64 + d0];
            float2 x01 = *(const float2*)&Qg[(size_t)r0*64 + d0 + 8];
            float2 x11 = *(const float2*)&Qg[(size_t)(r0+8)*64 + d0 + 8];
            split_pair(x00.x*QSCALE, x00.y*QSCALE, qh[s][0], ql[s][0]);
            split_pair(x10.x*QSCALE, x10.y*QSCALE, qh[s][1], ql[s][1]);
            split_pair(x01.x*QSCALE, x01.y*QSCALE, qh[s][2], ql[s][2]);
            split_pair(x11.x*QSCALE, x11.y*QSCALE, qh[s][3], ql[s][3]);
        }
    }

    float o_[8][4];
    #pragma unroll
    for (int j=0;j<8;j++){ o_[j][0]=0.f; o_[j][1]=0.f; o_[j][2]=0.f; o_[j][3]=0.f; }
    float l0s=0.f, l1s=0.f;

    for (int kt=0; kt<36; kt++){
        asm volatile("cp.async.wait_group 0;");
        __syncthreads();
        if (kt+1 < 36) { STAGE(kt+1, (kt+1)&1); }

        const uint4* Kt = sm4 + (kt&1)*2048;
        const uint4* Vt = Kt + 1024;

        float s_[8][4];
        #pragma unroll
        for (int j=0;j<8;j++){ s_[j][0]=0.f; s_[j][1]=0.f; s_[j][2]=0.f; s_[j][3]=0.f; }
        #pragma unroll
        for (int s=0;s<4;s++)
            #pragma unroll
            for (int nt=0;nt<8;nt++){
                uint4 kw = Kt[(s*8+nt)*32 + lane];
                mma16(s_[nt], qh[s], kw.x, kw.y);
                mma16(s_[nt], qh[s], kw.z, kw.w);
                mma16(s_[nt], ql[s], kw.x, kw.y);
            }

        #pragma unroll
        for (int j=0;j<8;j++){
            s_[j][0]=exp2f(s_[j][0]); s_[j][1]=exp2f(s_[j][1]);
            s_[j][2]=exp2f(s_[j][2]); s_[j][3]=exp2f(s_[j][3]);
            l0s += s_[j][0]+s_[j][1];
            l1s += s_[j][2]+s_[j][3];
        }

        uint32_t ph[4][4], pl[4][4];
        #pragma unroll
        for (int s2=0;s2<4;s2++){
            split_pair(s_[2*s2][0],   s_[2*s2][1],   ph[s2][0], pl[s2][0]);
            split_pair(s_[2*s2][2],   s_[2*s2][3],   ph[s2][1], pl[s2][1]);
            split_pair(s_[2*s2+1][0], s_[2*s2+1][1], ph[s2][2], pl[s2][2]);
            split_pair(s_[2*s2+1][2], s_[2*s2+1][3], ph[s2][3], pl[s2][3]);
        }

        #pragma unroll
        for (int s2=0;s2<4;s2++)
            #pragma unroll
            for (int j=0;j<8;j++){
                uint4 vw = Vt[(s2*8+j)*32 + lane];
                mma16(o_[j], ph[s2], vw.x, vw.y);
                mma16(o_[j], ph[s2], vw.z, vw.w);
                mma16(o_[j], pl[s2], vw.x, vw.y);
            }
    }
#undef STAGE

    l0s += __shfl_xor_sync(0xffffffffu, l0s, 1);
    l0s += __shfl_xor_sync(0xffffffffu, l0s, 2);
    l1s += __shfl_xor_sync(0xffffffffu, l1s, 1);
    l1s += __shfl_xor_sync(0xffffffffu, l1s, 2);
    float inv0 = 1.0f / l0s, inv1 = 1.0f / l1s;
    int q0 = qt*128 + w*16 + g;
    #pragma unroll
    for (int j=0;j<8;j++){
        int c = h*64 + j*8 + t*2;
        float2 v0 = make_float2(o_[j][0]*inv0, o_[j][1]*inv0);
        float2 v1 = make_float2(o_[j][2]*inv1, o_[j][3]*inv1);
        if (q0 < 1024){
            *(float2*)&outh[((size_t)b*1024 + q0)*1536 + c]     = v0;
            *(float2*)&outh[((size_t)b*1024 + q0 + 8)*1536 + c] = v1;
        } else {
            *(float2*)&oute[((size_t)b*256 + q0-1024)*1536 + c]     = v0;
            *(float2*)&oute[((size_t)b*256 + q0-1024 + 8)*1536 + c] = v1;
        }
    }
}

// ---------------- launch ----------------
extern "C" void kernel_launch(void* const* d_in, const int* in_sizes, int n_in,
                              void* d_out, int out_size)
{
    (void)in_sizes; (void)n_in; (void)out_size;
    const float* hs  = (const float*)d_in[0];
    const float* ehs = (const float*)d_in[1];
    const float* wq  = (const float*)d_in[2];  const float* bq  = (const float*)d_in[3];
    const float* wk  = (const float*)d_in[4];  const float* bk  = (const float*)d_in[5];
    const float* wv  = (const float*)d_in[6];  const float* bv  = (const float*)d_in[7];
    const float* awq = (const float*)d_in[8];  const float* abq = (const float*)d_in[9];
    const float* awk = (const float*)d_in[10]; const float* abk = (const float*)d_in[11];
    const float* awv = (const float*)d_in[12]; const float* abv = (const float*)d_in[13];
    const float* wo  = (const float*)d_in[14]; const float* bo  = (const float*)d_in[15];
    const float* wao = (const float*)d_in[16]; const float* bao = (const float*)d_in[17];
    float* out = (float*)d_out;

    float *q, *k, *v, *ah, *ae, *mq, *sq, *mk, *sk;
    uint4 *kf, *vf;
    cudaGetSymbolAddress((void**)&q,  g_q);
    cudaGetSymbolAddress((void**)&k,  g_k);
    cudaGetSymbolAddress((void**)&v,  g_v);
    cudaGetSymbolAddress((void**)&ah, g_ah);
    cudaGetSymbolAddress((void**)&ae, g_ae);
    cudaGetSymbolAddress((void**)&mq, g_mq);
    cudaGetSymbolAddress((void**)&sq, g_sq);
    cudaGetSymbolAddress((void**)&mk, g_mk);
    cudaGetSymbolAddress((void**)&sk, g_sk);
    cudaGetSymbolAddress((void**)&kf, g_kf);
    cudaGetSymbolAddress((void**)&vf, g_vf);

    static int attr_set = 0;
    if (!attr_set) {
        cudaFuncSetAttribute(gemm_qkv, cudaFuncAttributeMaxDynamicSharedMemorySize, GEMM_SMEM);
        cudaFuncSetAttribute(gemm_out, cudaFuncAttributeMaxDynamicSharedMemorySize, GEMM_SMEM);
        cudaFuncSetAttribute(attn_bf3, cudaFuncAttributeMaxDynamicSharedMemorySize, AT_SMEM);
        attr_set = 1;
    }

    // hidden QKV (fused over z): M=4096
    gemm_qkv<<<dim3(12, 32, 3), 512, GEMM_SMEM>>>(
        hs, wq, wk, wv, bq, bk, bv, q, k, v,
        1536, 1536, 1024, LQ, LK, LK, 0, 0, 0);
    // encoder QKV (fused over z): M=1024
    gemm_qkv<<<dim3(12, 8, 3), 512, GEMM_SMEM>>>(
        ehs, awq, awk, awv, abq, abk, abv, q, k, v,
        1536, 1536, 256, LQ, LK, LK, 1024, 2048, 2048);

    stats_kernel<<<96, 256>>>(q, LQ, mq, sq);
    stats_kernel<<<96, 256>>>(k, LK, mk, sk);
    adain_apply_kernel<<<6144, 256>>>(q, k, v, mq, sq, mk, sk);

    convert_k<<<dim3(36, 96), 256>>>(k, kf);
    convert_v<<<dim3(36, 96), 256>>>(v, vf);

    attn_bf3<<<dim3(10, 24, 4), 256, AT_SMEM>>>(q, kf, vf, ah, ae);

    // output projections (fused over z)
    gemm_out<<<dim3(12, 32, 2), 512, GEMM_SMEM>>>(
        ah, ae, wo, wao, bo, bao, out, out + (size_t)4096*1536, 1536, 1536);
}

// round 11
// speedup vs baseline: 1.3781x; 1.1338x over previous
#include <cuda_runtime.h>
#include <cuda_bf16.h>
#include <math.h>
#include <stdint.h>

#define NUM_H 24
#define LQ 1280
#define LK 2304

// ---------------- scratch (device globals; no allocations) ----------------
__device__ float g_q[4*24*1280*64];      // (B,H,LQ,64)
__device__ float g_k[4*24*2304*64];
__device__ float g_v[4*24*2304*64];
__device__ float g_ah[4*1024*1536];      // attention out, hidden part
__device__ float g_ae[4*256*1536];       // attention out, encoder part
__device__ float g_mq[6144], g_sq[6144], g_mk[6144], g_sk[6144];
__device__ float g_ps[96*4*64], g_pss[96*4*64];   // stats partials
// fragment-packed K/V for attention
__device__ uint4 g_kf[96*36*1024];
__device__ uint4 g_vf[96*36*1024];

// ---------------- bf16 helpers ----------------
__device__ __forceinline__ void split_pair(float x, float y, uint32_t &hi, uint32_t &lo){
    __nv_bfloat162 hv = __floats2bfloat162_rn(x, y);
    hi = *reinterpret_cast<uint32_t*>(&hv);
    float rx = x - __low2float(hv);
    float ry = y - __high2float(hv);
    __nv_bfloat162 lv = __floats2bfloat162_rn(rx, ry);
    lo = *reinterpret_cast<uint32_t*>(&lv);
}

__device__ __forceinline__ void mma16(float* c, const uint32_t* a, uint32_t b0, uint32_t b1){
    asm volatile("mma.sync.aligned.m16n8k16.row.col.f32.bf16.bf16.f32 "
        "{%0,%1,%2,%3},{%4,%5,%6,%7},{%8,%9},{%0,%1,%2,%3};"
        : "+f"(c[0]),"+f"(c[1]),"+f"(c[2]),"+f"(c[3])
        : "r"(a[0]),"r"(a[1]),"r"(a[2]),"r"(a[3]),"r"(b0),"r"(b1));
}

__device__ __forceinline__ void ldsm4(uint32_t* r, uint32_t addr){
    asm volatile("ldmatrix.sync.aligned.m8n8.x4.shared.b16 {%0,%1,%2,%3}, [%4];"
        : "=r"(r[0]),"=r"(r[1]),"=r"(r[2]),"=r"(r[3]) : "r"(addr));
}

__device__ __forceinline__ void cp16(uint32_t saddr, const void* gptr){
    asm volatile("cp.async.cg.shared.global [%0], [%1], 16;" :: "r"(saddr), "l"(gptr));
}

// ================= split-bf16 GEMM: 128x128 tile, BK=32, 512 threads ========
#define GBUF 8192
#define GEMM_SMEM (2*GBUF*4)   // 65536 B

__device__ __forceinline__ void gemm_core(
    const float* __restrict__ A, const float* __restrict__ W,
    const float* __restrict__ bias, float* __restrict__ out,
    int K, int N, int heads_mode, int S_rows, int L, int s_off,
    int row0, int col0, uint32_t* sm)
{
    const int tid = threadIdx.x, lane = tid & 31, wrp = tid >> 5;
    const int g = lane >> 2, t = lane & 3;
    const int wm = wrp >> 2, wn = wrp & 3;

    float acc[2][4][4];
    #pragma unroll
    for (int i=0;i<2;i++)
        #pragma unroll
        for (int j=0;j<4;j++)
            #pragma unroll
            for (int r=0;r<4;r++) acc[i][j][r]=0.f;

    const int am0 = tid >> 3;
    const int ak4 = tid & 7;
    const int bs  = tid >> 8;
    const int bt  = (tid >> 6) & 3;
    const int bn  = (tid & 63) * 2;

    const uint32_t sbase = (uint32_t)__cvta_generic_to_shared(sm);
    uint32_t a_off[2][2];
    #pragma unroll
    for (int mt=0; mt<2; mt++){
        int r = wm*32 + mt*16 + ((lane>>3)&1)*8 + (lane&7);
        int swz = (r>>1)&3;
        #pragma unroll
        for (int s=0; s<2; s++){
            int u = s*2 + (lane>>4);
            a_off[mt][s] = (uint32_t)(r*64 + ((u ^ swz)<<4));
        }
    }
    uint32_t b_slot[2][4];
    #pragma unroll
    for (int s=0; s<2; s++)
        #pragma unroll
        for (int nt=0; nt<4; nt++){
            int ntg = wn*4 + nt;
            int lp = ((g*4+t) ^ (g>>1)) ^ ((ntg&1)<<2);
            b_slot[s][nt] = (uint32_t)((s*16+ntg)*32 + lp);
        }

    float4 ra[2];
    float2 rb[4];
    const int nT = K >> 5;

#define LOADG(tk) { \
    const float* Ab = A + (size_t)row0 * K + (tk)*32; \
    ra[0] = *(const float4*)&Ab[(size_t)am0*K + ak4*4]; \
    ra[1] = *(const float4*)&Ab[(size_t)(am0+64)*K + ak4*4]; \
    const float* Wb = W + (size_t)((tk)*32 + bs*16 + 2*bt)*N + col0 + bn; \
    rb[0] = *(const float2*)Wb; \
    rb[1] = *(const float2*)(Wb + N); \
    rb[2] = *(const float2*)(Wb + 8*(size_t)N); \
    rb[3] = *(const float2*)(Wb + 9*(size_t)N); }

#define STOREB(buf) { \
    uint32_t* Ah = (buf); uint32_t* Al = (buf)+2048; \
    uint4* Bp = (uint4*)((buf)+4096); \
    _Pragma("unroll") \
    for (int i=0;i<2;i++){ \
        int r = am0 + i*64; \
        uint2 hv, lv; \
        split_pair(ra[i].x, ra[i].y, hv.x, lv.x); \
        split_pair(ra[i].z, ra[i].w, hv.y, lv.y); \
        int o = r*16 + (((ak4>>1) ^ ((r>>1)&3))<<2) + (ak4&1)*2; \
        *(uint2*)&Ah[o] = hv; *(uint2*)&Al[o] = lv; \
    } \
    { \
        uint4 w4; \
        split_pair(rb[0].x, rb[1].x, w4.x, w4.z); \
        split_pair(rb[2].x, rb[3].x, w4.y, w4.w); \
        int n0 = bn, ntg = n0>>3, gg = n0&7; \
        int lp = ((gg*4+bt) ^ (gg>>1)) ^ ((ntg&1)<<2); \
        Bp[(bs*16+ntg)*32 + lp] = w4; \
        split_pair(rb[0].y, rb[1].y, w4.x, w4.z); \
        split_pair(rb[2].y, rb[3].y, w4.y, w4.w); \
        int n1 = bn+1; ntg = n1>>3; gg = n1&7; \
        lp = ((gg*4+bt) ^ (gg>>1)) ^ ((ntg&1)<<2); \
        Bp[(bs*16+ntg)*32 + lp] = w4; \
    } }

    LOADG(0);
    STOREB(sm);
    __syncthreads();

    for (int tk=0; tk<nT; tk++){
        uint32_t* buf = sm + (tk&1)*GBUF;
        const uint32_t bufb = sbase + (uint32_t)(tk&1)*(GBUF*4);
        if (tk+1 < nT) LOADG(tk+1);
        const uint4* Bp = (const uint4*)(buf+4096);
        #pragma unroll
        for (int s=0;s<2;s++){
            uint32_t ah[2][4], al[2][4];
            #pragma unroll
            for (int mt=0;mt<2;mt++){
                ldsm4(ah[mt], bufb + a_off[mt][s]);
                ldsm4(al[mt], bufb + 8192u + a_off[mt][s]);
            }
            #pragma unroll
            for (int nt=0;nt<4;nt++){
                uint4 kw = Bp[b_slot[s][nt]];
                #pragma unroll
                for (int mt=0;mt<2;mt++){
                    mma16(acc[mt][nt], ah[mt], kw.x, kw.y);
                    mma16(acc[mt][nt], ah[mt], kw.z, kw.w);
                    mma16(acc[mt][nt], al[mt], kw.x, kw.y);
                }
            }
        }
        if (tk+1 < nT) { STOREB(sm + ((tk+1)&1)*GBUF); }
        __syncthreads();
    }

    #pragma unroll
    for (int mt=0;mt<2;mt++){
        int m0r = row0 + wm*32 + mt*16 + g;
        #pragma unroll
        for (int nt=0;nt<4;nt++){
            int c = col0 + wn*32 + nt*8 + t*2;
            float b0v = bias[c], b1v = bias[c+1];
            float2 v0 = make_float2(acc[mt][nt][0]+b0v, acc[mt][nt][1]+b1v);
            float2 v1 = make_float2(acc[mt][nt][2]+b0v, acc[mt][nt][3]+b1v);
            if (!heads_mode){
                *(float2*)&out[(size_t)m0r*N + c]     = v0;
                *(float2*)&out[(size_t)(m0r+8)*N + c] = v1;
            } else {
                int hh = c >> 6, hd = c & 63;
                int bb = m0r / S_rows, ss = m0r - bb*S_rows;
                *(float2*)&out[((size_t)(bb*NUM_H+hh)*L + s_off + ss)*64 + hd] = v0;
                int m1r = m0r + 8;
                int bb1 = m1r / S_rows, ss1 = m1r - bb1*S_rows;
                *(float2*)&out[((size_t)(bb1*NUM_H+hh)*L + s_off + ss1)*64 + hd] = v1;
            }
        }
    }
#undef LOADG
#undef STOREB
}

__global__ void __launch_bounds__(512, 1) gemm_qkv(
    const float* __restrict__ A,
    const float* __restrict__ W0, const float* __restrict__ W1, const float* __restrict__ W2,
    const float* __restrict__ b0, const float* __restrict__ b1, const float* __restrict__ b2,
    float* __restrict__ o0, float* __restrict__ o1, float* __restrict__ o2,
    int K, int N, int S_rows, int L0, int L1, int L2,
    int soff0, int soff1, int soff2)
{
    extern __shared__ uint32_t sm[];
    const int z = blockIdx.z;
    const float* W = (z==0)? W0 : (z==1)? W1 : W2;
    const float* bi = (z==0)? b0 : (z==1)? b1 : b2;
    float* out = (z==0)? o0 : (z==1)? o1 : o2;
    int L = (z==0)? L0 : (z==1)? L1 : L2;
    int soff = (z==0)? soff0 : (z==1)? soff1 : soff2;
    gemm_core(A, W, bi, out, K, N, 1, S_rows, L, soff,
              blockIdx.y*128, blockIdx.x*128, sm);
}

__global__ void __launch_bounds__(512, 1) gemm_out(
    const float* __restrict__ A0, const float* __restrict__ A1,
    const float* __restrict__ W0, const float* __restrict__ W1,
    const float* __restrict__ b0, const float* __restrict__ b1,
    float* __restrict__ o0, float* __restrict__ o1,
    int K, int N)
{
    extern __shared__ uint32_t sm[];
    const int z = blockIdx.z;
    if (z == 1 && blockIdx.y >= 8) return;
    const float* A = (z==0)? A0 : A1;
    const float* W = (z==0)? W0 : W1;
    const float* bi = (z==0)? b0 : b1;
    float* out = (z==0)? o0 : o1;
    gemm_core(A, W, bi, out, K, N, 0, 0, 0, 0,
              blockIdx.y*128, blockIdx.x*128, sm);
}

// ---------------- two-phase stats: partials then finalize ----------------
__global__ void __launch_bounds__(256) stats_part(
    const float* __restrict__ buf, int L,
    float* __restrict__ ps, float* __restrict__ pss)
{
    const int bh = blockIdx.x, part = blockIdx.y;
    const int tx = threadIdx.x & 63;
    const int ty = threadIdx.x >> 6;
    const float* p = buf + (size_t)bh * L * 64;
    float s = 0.f, ss = 0.f;
    for (int i = part*256 + ty; i < part*256 + 256; i += 4) {
        float v = p[(size_t)i*64 + tx];
        s += v; ss += v*v;
    }
    __shared__ float sh1[4][64], sh2[4][64];
    sh1[ty][tx] = s; sh2[ty][tx] = ss;
    __syncthreads();
    if (ty == 0) {
        ps [(bh*4+part)*64 + tx] = sh1[0][tx]+sh1[1][tx]+sh1[2][tx]+sh1[3][tx];
        pss[(bh*4+part)*64 + tx] = sh2[0][tx]+sh2[1][tx]+sh2[2][tx]+sh2[3][tx];
    }
}

__global__ void __launch_bounds__(64) stats_fin(
    const float* __restrict__ ps, const float* __restrict__ pss,
    float* __restrict__ mean, float* __restrict__ stdev)
{
    const int bh = blockIdx.x, tx = threadIdx.x;
    float s = 0.f, ss = 0.f;
    #pragma unroll
    for (int p=0;p<4;p++){
        s  += ps [(bh*4+p)*64 + tx];
        ss += pss[(bh*4+p)*64 + tx];
    }
    float m = s * (1.0f/1024.0f);
    float var = (ss - 1024.0f*m*m) * (1.0f/1023.0f);
    mean[bh*64+tx]  = m;
    stdev[bh*64+tx] = sqrtf(var + 1e-5f);
}

// ---------------- AdaIN apply: q only (odd b) ----------------
__global__ void adain_q_kernel(
    float* __restrict__ q,
    const float* __restrict__ mq, const float* __restrict__ sq)
{
    const int idx = blockIdx.x * 256 + threadIdx.x;
    if (idx >= 2*24*1024*16) return;
    const int c  = (idx & 15) * 4;
    const int s  = (idx >> 4) & 1023;
    const int bhh = idx >> 14;            // 0..47
    const int bo = bhh / 24, h = bhh - bo*24;
    const int b  = 2*bo + 1;
    const int bh = b*24 + h;
    const int sbh = (b-1)*24 + h;

    const int ib = bh*64 + c, is = sbh*64 + c;
    float4 mb = *(const float4*)&mq[ib], sb = *(const float4*)&sq[ib];
    float4 ms = *(const float4*)&mq[is], so = *(const float4*)&sq[is];
    const size_t qi = ((size_t)bh*LQ + s)*64 + c;
    float4 x = *(const float4*)&q[qi];
    x.x = (x.x - mb.x)/sb.x*so.x + ms.x;
    x.y = (x.y - mb.y)/sb.y*so.y + ms.y;
    x.z = (x.z - mb.z)/sb.z*so.z + ms.z;
    x.w = (x.w - mb.w)/sb.w*so.w + ms.w;
    *(float4*)&q[qi] = x;
}

// ---------------- fused convert K: source remap + adain styling ----------
// kt<16: own rows, styled if b odd.  16<=kt<32: src-batch raw rows (only
// needed for odd b; even b skips — attn uses duplicated first half).
// kt>=32: encoder rows as-is.
__global__ void __launch_bounds__(256) convert_k(
    const float* __restrict__ k,
    const float* __restrict__ mk, const float* __restrict__ sk,
    uint4* __restrict__ kf)
{
    const int kt = blockIdx.x, bh = blockIdx.y;
    const int b = bh / 24, h = bh - b*24;
    const bool odd = (b & 1);
    if (!odd && kt >= 16 && kt < 32) return;

    __shared__ float sK[64][65];
    __shared__ float pa[64], pc[64];
    const int tid = threadIdx.x;

    const float* src;
    bool style = false;
    if (kt < 16){ src = k + ((size_t)bh*LK + kt*64)*64; style = odd; }
    else if (kt < 32){ int sbh = (b-1)*24 + h; src = k + ((size_t)sbh*LK + (kt-16)*64)*64; }
    else { src = k + ((size_t)bh*LK + kt*64)*64; }

    if (style && tid < 64){
        int sbh = (b-1)*24 + h;
        float a = sk[sbh*64+tid] / sk[bh*64+tid];
        pa[tid] = a;
        pc[tid] = mk[sbh*64+tid] - mk[bh*64+tid]*a;
    }
    __syncthreads();
    #pragma unroll
    for (int i=0;i<16;i++){
        int e = tid + i*256;
        float x = src[e];
        if (style) x = fmaf(x, pa[e&63], pc[e&63]);
        sK[e>>6][e&63] = x;
    }
    __syncthreads();
    uint4* dst = kf + ((size_t)bh*36 + kt)*1024;
    #pragma unroll
    for (int i=0;i<4;i++){
        int slot = tid + i*256;
        int lane = slot & 31, nt = (slot>>5)&7, s = slot>>8;
        int g = lane>>2, t = lane&3;
        int kv = nt*8+g, d0 = 16*s+2*t;
        uint4 w4;
        split_pair(sK[kv][d0],   sK[kv][d0+1], w4.x, w4.z);
        split_pair(sK[kv][d0+8], sK[kv][d0+9], w4.y, w4.w);
        dst[slot] = w4;
    }
}

__global__ void __launch_bounds__(256) convert_v(
    const float* __restrict__ v, uint4* __restrict__ vf)
{
    const int kt = blockIdx.x, bh = blockIdx.y;
    const int b = bh / 24, h = bh - b*24;
    const bool odd = (b & 1);
    if (!odd && kt >= 16 && kt < 32) return;

    __shared__ float sV[64][65];
    const int tid = threadIdx.x;
    const float* src;
    if (kt < 32 && kt >= 16){ int sbh = (b-1)*24 + h; src = v + ((size_t)sbh*LK + (kt-16)*64)*64; }
    else { src = v + ((size_t)bh*LK + kt*64)*64; }

    #pragma unroll
    for (int i=0;i<16;i++){
        int e = tid + i*256;
        sV[e>>6][e&63] = src[e];
    }
    __syncthreads();
    uint4* dst = vf + ((size_t)bh*36 + kt)*1024;
    #pragma unroll
    for (int i=0;i<4;i++){
        int slot = tid + i*256;
        int lane = slot & 31, j = (slot>>5)&7, s2 = slot>>8;
        int g = lane>>2, t = lane&3;
        int d = j*8+g, r0 = 16*s2+2*t;
        uint4 w4;
        split_pair(sV[r0][d],   sV[r0+1][d], w4.x, w4.z);
        split_pair(sV[r0+8][d], sV[r0+9][d], w4.y, w4.w);
        dst[slot] = w4;
    }
}

// ================= split-bf16 flash attention, max-free softmax =============
// Even b: kv[1024:2048]==kv[0:1024] (STYLE_IDX self-map), so process tiles
// 0..15 with exp2(s+1) (exact doubling of both P and lsum) + tiles 32..35.
#define AT_SMEM (2*2048*16)

__global__ void __launch_bounds__(256, 2) attn_bf3(
    const float* __restrict__ Q,
    const uint4* __restrict__ KF, const uint4* __restrict__ VF,
    float* __restrict__ outh, float* __restrict__ oute)
{
    extern __shared__ uint4 sm4[];
    const int tid = threadIdx.x, lane = tid & 31, w = tid >> 5;
    const int g = lane >> 2, t = lane & 3;
    const int qt = blockIdx.x, h = blockIdx.y, b = blockIdx.z;
    const bool odd = (b & 1);
    const int nkt = odd ? 36 : 20;
    const size_t bh = (size_t)b*NUM_H + h;
    const float* Qg = Q + (bh*LQ + (size_t)qt*128) * 64;
    const uint4* Kg = KF + bh*36*1024;
    const uint4* Vg = VF + bh*36*1024;
    const uint32_t smem_base = (uint32_t)__cvta_generic_to_shared(sm4);
    const float QSCALE = 0.125f * 1.44269504088896f;

#define KTOF(j_) ((odd || (j_) < 16) ? (j_) : (j_) + 16)
#define STAGE(kt_, buf_) { \
    uint32_t sb = smem_base + (buf_)*32768u; \
    const uint4* kp = Kg + (size_t)(kt_)*1024 + tid; \
    const uint4* vp = Vg + (size_t)(kt_)*1024 + tid; \
    _Pragma("unroll") \
    for (int i_=0;i_<4;i_++){ \
        cp16(sb + (uint32_t)(tid + i_*256)*16u,           kp + i_*256); \
        cp16(sb + 16384u + (uint32_t)(tid + i_*256)*16u,  vp + i_*256); \
    } \
    asm volatile("cp.async.commit_group;"); }

    STAGE(0, 0);

    uint32_t qh[4][4], ql[4][4];
    {
        const int r0 = w*16 + g;
        #pragma unroll
        for (int s=0;s<4;s++){
            int d0 = 16*s + 2*t;
            float2 x00 = *(const float2*)&Qg[(size_t)r0*64 + d0];
            float2 x10 = *(const float2*)&Qg[(size_t)(r0+8)*64 + d0];
            float2 x01 = *(const float2*)&Qg[(size_t)r0*64 + d0 + 8];
            float2 x11 = *(const float2*)&Qg[(size_t)(r0+8)*64 + d0 + 8];
            split_pair(x00.x*QSCALE, x00.y*QSCALE, qh[s][0], ql[s][0]);
            split_pair(x10.x*QSCALE, x10.y*QSCALE, qh[s][1], ql[s][1]);
            split_pair(x01.x*QSCALE, x01.y*QSCALE, qh[s][2], ql[s][2]);
            split_pair(x11.x*QSCALE, x11.y*QSCALE, qh[s][3], ql[s][3]);
        }
    }

    float o_[8][4];
    #pragma unroll
    for (int j=0;j<8;j++){ o_[j][0]=0.f; o_[j][1]=0.f; o_[j][2]=0.f; o_[j][3]=0.f; }
    float l0s=0.f, l1s=0.f;

    for (int jj=0; jj<nkt; jj++){
        asm volatile("cp.async.wait_group 0;");
        __syncthreads();
        if (jj+1 < nkt) { STAGE(KTOF(jj+1), (jj+1)&1); }

        const uint4* Kt = sm4 + (jj&1)*2048;
        const uint4* Vt = Kt + 1024;
        const float padd = (!odd && jj < 16) ? 1.0f : 0.0f;  // exact x2 weight

        float s_[8][4];
        #pragma unroll
        for (int j=0;j<8;j++){ s_[j][0]=0.f; s_[j][1]=0.f; s_[j][2]=0.f; s_[j][3]=0.f; }
        #pragma unroll
        for (int s=0;s<4;s++)
            #pragma unroll
            for (int nt=0;nt<8;nt++){
                uint4 kw = Kt[(s*8+nt)*32 + lane];
                mma16(s_[nt], qh[s], kw.x, kw.y);
                mma16(s_[nt], qh[s], kw.z, kw.w);
                mma16(s_[nt], ql[s], kw.x, kw.y);
            }

        #pragma unroll
        for (int j=0;j<8;j++){
            s_[j][0]=exp2f(s_[j][0]+padd); s_[j][1]=exp2f(s_[j][1]+padd);
            s_[j][2]=exp2f(s_[j][2]+padd); s_[j][3]=exp2f(s_[j][3]+padd);
            l0s += s_[j][0]+s_[j][1];
            l1s += s_[j][2]+s_[j][3];
        }

        uint32_t ph[4][4], pl[4][4];
        #pragma unroll
        for (int s2=0;s2<4;s2++){
            split_pair(s_[2*s2][0],   s_[2*s2][1],   ph[s2][0], pl[s2][0]);
            split_pair(s_[2*s2][2],   s_[2*s2][3],   ph[s2][1], pl[s2][1]);
            split_pair(s_[2*s2+1][0], s_[2*s2+1][1], ph[s2][2], pl[s2][2]);
            split_pair(s_[2*s2+1][2], s_[2*s2+1][3], ph[s2][3], pl[s2][3]);
        }

        #pragma unroll
        for (int s2=0;s2<4;s2++)
            #pragma unroll
            for (int j=0;j<8;j++){
                uint4 vw = Vt[(s2*8+j)*32 + lane];
                mma16(o_[j], ph[s2], vw.x, vw.y);
                mma16(o_[j], ph[s2], vw.z, vw.w);
                mma16(o_[j], pl[s2], vw.x, vw.y);
            }
    }
#undef STAGE
#undef KTOF

    l0s += __shfl_xor_sync(0xffffffffu, l0s, 1);
    l0s += __shfl_xor_sync(0xffffffffu, l0s, 2);
    l1s += __shfl_xor_sync(0xffffffffu, l1s, 1);
    l1s += __shfl_xor_sync(0xffffffffu, l1s, 2);
    float inv0 = 1.0f / l0s, inv1 = 1.0f / l1s;
    int q0 = qt*128 + w*16 + g;
    #pragma unroll
    for (int j=0;j<8;j++){
        int c = h*64 + j*8 + t*2;
        float2 v0 = make_float2(o_[j][0]*inv0, o_[j][1]*inv0);
        float2 v1 = make_float2(o_[j][2]*inv1, o_[j][3]*inv1);
        if (q0 < 1024){
            *(float2*)&outh[((size_t)b*1024 + q0)*1536 + c]     = v0;
            *(float2*)&outh[((size_t)b*1024 + q0 + 8)*1536 + c] = v1;
        } else {
            *(float2*)&oute[((size_t)b*256 + q0-1024)*1536 + c]     = v0;
            *(float2*)&oute[((size_t)b*256 + q0-1024 + 8)*1536 + c] = v1;
        }
    }
}

// ---------------- launch ----------------
extern "C" void kernel_launch(void* const* d_in, const int* in_sizes, int n_in,
                              void* d_out, int out_size)
{
    (void)in_sizes; (void)n_in; (void)out_size;
    const float* hs  = (const float*)d_in[0];
    const float* ehs = (const float*)d_in[1];
    const float* wq  = (const float*)d_in[2];  const float* bq  = (const float*)d_in[3];
    const float* wk  = (const float*)d_in[4];  const float* bk  = (const float*)d_in[5];
    const float* wv  = (const float*)d_in[6];  const float* bv  = (const float*)d_in[7];
    const float* awq = (const float*)d_in[8];  const float* abq = (const float*)d_in[9];
    const float* awk = (const float*)d_in[10]; const float* abk = (const float*)d_in[11];
    const float* awv = (const float*)d_in[12]; const float* abv = (const float*)d_in[13];
    const float* wo  = (const float*)d_in[14]; const float* bo  = (const float*)d_in[15];
    const float* wao = (const float*)d_in[16]; const float* bao = (const float*)d_in[17];
    float* out = (float*)d_out;

    float *q, *k, *v, *ah, *ae, *mq, *sq, *mk, *sk, *ps, *pss;
    uint4 *kf, *vf;
    cudaGetSymbolAddress((void**)&q,  g_q);
    cudaGetSymbolAddress((void**)&k,  g_k);
    cudaGetSymbolAddress((void**)&v,  g_v);
    cudaGetSymbolAddress((void**)&ah, g_ah);
    cudaGetSymbolAddress((void**)&ae, g_ae);
    cudaGetSymbolAddress((void**)&mq, g_mq);
    cudaGetSymbolAddress((void**)&sq, g_sq);
    cudaGetSymbolAddress((void**)&mk, g_mk);
    cudaGetSymbolAddress((void**)&sk, g_sk);
    cudaGetSymbolAddress((void**)&ps, g_ps);
    cudaGetSymbolAddress((void**)&pss, g_pss);
    cudaGetSymbolAddress((void**)&kf, g_kf);
    cudaGetSymbolAddress((void**)&vf, g_vf);

    static int attr_set = 0;
    if (!attr_set) {
        cudaFuncSetAttribute(gemm_qkv, cudaFuncAttributeMaxDynamicSharedMemorySize, GEMM_SMEM);
        cudaFuncSetAttribute(gemm_out, cudaFuncAttributeMaxDynamicSharedMemorySize, GEMM_SMEM);
        cudaFuncSetAttribute(attn_bf3, cudaFuncAttributeMaxDynamicSharedMemorySize, AT_SMEM);
        attr_set = 1;
    }

    // hidden + encoder QKV (fused over z)
    gemm_qkv<<<dim3(12, 32, 3), 512, GEMM_SMEM>>>(
        hs, wq, wk, wv, bq, bk, bv, q, k, v,
        1536, 1536, 1024, LQ, LK, LK, 0, 0, 0);
    gemm_qkv<<<dim3(12, 8, 3), 512, GEMM_SMEM>>>(
        ehs, awq, awk, awv, abq, abk, abv, q, k, v,
        1536, 1536, 256, LQ, LK, LK, 1024, 2048, 2048);

    // stats (two-phase)
    stats_part<<<dim3(96, 4), 256>>>(q, LQ, ps, pss);
    stats_fin<<<96, 64>>>(ps, pss, mq, sq);
    stats_part<<<dim3(96, 4), 256>>>(k, LK, ps, pss);
    stats_fin<<<96, 64>>>(ps, pss, mk, sk);

    // q styling + fused K/V conversion (styling + replication + packing)
    adain_q_kernel<<<3072, 256>>>(q, mq, sq);
    convert_k<<<dim3(36, 96), 256>>>(k, mk, sk, kf);
    convert_v<<<dim3(36, 96), 256>>>(v, vf);

    attn_bf3<<<dim3(10, 24, 4), 256, AT_SMEM>>>(q, kf, vf, ah, ae);

    // output projections (fused over z)
    gemm_out<<<dim3(12, 32, 2), 512, GEMM_SMEM>>>(
        ah, ae, wo, wao, bo, bao, out, out + (size_t)4096*1536, 1536, 1536);
}